// round 4
// baseline (speedup 1.0000x reference)
#include <cuda_runtime.h>
#include <cuda_bf16.h>
#include <math.h>

// Problem constants (fixed by reference)
#define NN     50000
#define EDGES  800000
#define F_IN   256
#define HIDC   128
#define NHEAD  4
#define CATC   512   // NHEAD*HIDC
#define OUTC   256

// ---------------- device scratch (static globals; no allocation) ------------
__device__ float g_h[(size_t)NN * CATC];     // GEMM outputs per layer (102.4 MB)
__device__ float g_feat[(size_t)NN * CATC];  // aggregated/activated features (102.4 MB)
__device__ float g_als[NN * NHEAD];
__device__ float g_ald[NN * NHEAD];
__device__ int   g_deg[NN];
__device__ int   g_cur[NN];
__device__ int   g_off[NN + 1];
__device__ int   g_csrc[EDGES];

// ---------------- CSR build -------------------------------------------------
__global__ void k_zero_deg() {
    int i = blockIdx.x * blockDim.x + threadIdx.x;
    if (i < NN) g_deg[i] = 0;
}

__global__ void k_count(const int* __restrict__ ei) {
    int e = blockIdx.x * blockDim.x + threadIdx.x;
    if (e < EDGES) atomicAdd(&g_deg[ei[EDGES + e]], 1);
}

// single-block exclusive scan of g_deg -> g_off (N=50000, 49 iters of 1024)
__global__ void k_scan() {
    __shared__ int wsum[32];
    __shared__ int carry_s;
    int t = threadIdx.x;
    int lane = t & 31, wid = t >> 5;
    if (t == 0) carry_s = 0;
    __syncthreads();
    for (int base = 0; base < NN; base += 1024) {
        int i = base + t;
        int v = (i < NN) ? g_deg[i] : 0;
        int x = v;
        #pragma unroll
        for (int o = 1; o < 32; o <<= 1) {
            int y = __shfl_up_sync(0xFFFFFFFFu, x, o);
            if (lane >= o) x += y;
        }
        if (lane == 31) wsum[wid] = x;
        __syncthreads();
        if (wid == 0) {
            int ws = wsum[lane];
            #pragma unroll
            for (int o = 1; o < 32; o <<= 1) {
                int y = __shfl_up_sync(0xFFFFFFFFu, ws, o);
                if (lane >= o) ws += y;
            }
            wsum[lane] = ws;
        }
        __syncthreads();
        int incl = x + (wid ? wsum[wid - 1] : 0);
        int total = wsum[31];
        int carry = carry_s;
        if (i < NN) g_off[i] = carry + incl - v;   // exclusive
        __syncthreads();
        if (t == 0) carry_s = carry + total;
        __syncthreads();
    }
    if (t == 0) g_off[NN] = carry_s;
}

__global__ void k_cursor_init() {
    int i = blockIdx.x * blockDim.x + threadIdx.x;
    if (i < NN) g_cur[i] = g_off[i];
}

__global__ void k_scatter(const int* __restrict__ ei) {
    int e = blockIdx.x * blockDim.x + threadIdx.x;
    if (e < EDGES) {
        int s = ei[e], d = ei[EDGES + e];
        int p = atomicAdd(&g_cur[d], 1);
        g_csrc[p] = s;
    }
}

// ---------------- attention logit dot products ------------------------------
// warp per node, 512-ch / 4 heads
__global__ void k_alpha4(const float* __restrict__ hbuf,
                         const float* __restrict__ asrc,
                         const float* __restrict__ adst,
                         float* __restrict__ als, float* __restrict__ ald) {
    int w = (blockIdx.x * blockDim.x + threadIdx.x) >> 5;
    int lane = threadIdx.x & 31;
    if (w >= NN) return;
    const float* hv = hbuf + (size_t)w * CATC;
    float ps[4] = {0.f, 0.f, 0.f, 0.f}, pd[4] = {0.f, 0.f, 0.f, 0.f};
    #pragma unroll
    for (int k = 0; k < 16; k++) {
        int c = k * 32 + lane;
        float h = hv[c];
        int hh = k >> 2;
        int cc = (k & 3) * 32 + lane;
        ps[hh] += h * __ldg(asrc + hh * HIDC + cc);
        pd[hh] += h * __ldg(adst + hh * HIDC + cc);
    }
    #pragma unroll
    for (int hh = 0; hh < 4; hh++) {
        #pragma unroll
        for (int o = 16; o; o >>= 1) {
            ps[hh] += __shfl_xor_sync(0xFFFFFFFFu, ps[hh], o);
            pd[hh] += __shfl_xor_sync(0xFFFFFFFFu, pd[hh], o);
        }
    }
    if (lane == 0) {
        float4 s4 = make_float4(ps[0], ps[1], ps[2], ps[3]);
        float4 d4 = make_float4(pd[0], pd[1], pd[2], pd[3]);
        *(float4*)(als + 4 * w) = s4;
        *(float4*)(ald + 4 * w) = d4;
    }
}

// warp per node, 256-ch / 1 head
__global__ void k_alpha1(const float* __restrict__ hbuf,
                         const float* __restrict__ asrc,
                         const float* __restrict__ adst,
                         float* __restrict__ als, float* __restrict__ ald) {
    int w = (blockIdx.x * blockDim.x + threadIdx.x) >> 5;
    int lane = threadIdx.x & 31;
    if (w >= NN) return;
    const float* hv = hbuf + (size_t)w * OUTC;
    float ps = 0.f, pd = 0.f;
    #pragma unroll
    for (int k = 0; k < 8; k++) {
        int c = k * 32 + lane;
        float h = hv[c];
        ps += h * __ldg(asrc + c);
        pd += h * __ldg(adst + c);
    }
    #pragma unroll
    for (int o = 16; o; o >>= 1) {
        ps += __shfl_xor_sync(0xFFFFFFFFu, ps, o);
        pd += __shfl_xor_sync(0xFFFFFFFFu, pd, o);
    }
    if (lane == 0) { als[w] = ps; ald[w] = pd; }
}

__device__ __forceinline__ float leaky02(float x) { return x > 0.f ? x : 0.2f * x; }

// ---------------- per-dst segment softmax + weighted aggregation ------------
// 4 heads x 128 ch, warp per node, online softmax; epilogue: +bias, ELU
__global__ void k_agg512(const float* __restrict__ hbuf,
                         const float* __restrict__ als,
                         const float* __restrict__ ald,
                         const float* __restrict__ bias,
                         float* __restrict__ out) {
    int w = (blockIdx.x * blockDim.x + threadIdx.x) >> 5;
    int lane = threadIdx.x & 31;
    if (w >= NN) return;

    float4 adv = __ldg((const float4*)(ald + 4 * w));
    float ad[4] = {adv.x, adv.y, adv.z, adv.w};
    float4 asv = __ldg((const float4*)(als + 4 * w));
    float m[4], dnm[4], acc[16];
    // self loop seeds the online softmax (weight exp(0)=1)
    m[0] = leaky02(asv.x + ad[0]); m[1] = leaky02(asv.y + ad[1]);
    m[2] = leaky02(asv.z + ad[2]); m[3] = leaky02(asv.w + ad[3]);
    dnm[0] = dnm[1] = dnm[2] = dnm[3] = 1.f;
    const float* hv = hbuf + (size_t)w * CATC;
    #pragma unroll
    for (int k = 0; k < 16; k++) acc[k] = hv[k * 32 + lane];

    int beg = g_off[w], end = g_off[w + 1];
    for (int p = beg; p < end; p++) {
        int u = g_csrc[p];
        float4 asu = __ldg((const float4*)(als + 4 * u));
        float ev[4] = {leaky02(asu.x + ad[0]), leaky02(asu.y + ad[1]),
                       leaky02(asu.z + ad[2]), leaky02(asu.w + ad[3])};
        float w4[4];
        #pragma unroll
        for (int hh = 0; hh < 4; hh++) {
            float e = ev[hh];
            if (e > m[hh]) {
                float s = __expf(m[hh] - e);
                dnm[hh] *= s;
                acc[4 * hh + 0] *= s; acc[4 * hh + 1] *= s;
                acc[4 * hh + 2] *= s; acc[4 * hh + 3] *= s;
                m[hh] = e;
                w4[hh] = 1.f;
            } else {
                w4[hh] = __expf(e - m[hh]);
            }
            dnm[hh] += w4[hh];
        }
        const float* hu = hbuf + (size_t)u * CATC;
        #pragma unroll
        for (int k = 0; k < 16; k++)
            acc[k] += w4[k >> 2] * __ldg(hu + k * 32 + lane);
    }
    float* ov = out + (size_t)w * CATC;
    #pragma unroll
    for (int k = 0; k < 16; k++) {
        int c = k * 32 + lane;
        float v = acc[k] / dnm[k >> 2] + __ldg(bias + c);
        v = v > 0.f ? v : (__expf(v) - 1.f);   // ELU
        ov[c] = v;
    }
}

// 1 head x 256 ch, warp per node; epilogue: +bias, no activation
__global__ void k_agg256(const float* __restrict__ hbuf,
                         const float* __restrict__ als,
                         const float* __restrict__ ald,
                         const float* __restrict__ bias,
                         float* __restrict__ out) {
    int w = (blockIdx.x * blockDim.x + threadIdx.x) >> 5;
    int lane = threadIdx.x & 31;
    if (w >= NN) return;

    float ad = __ldg(ald + w);
    float m = leaky02(__ldg(als + w) + ad);
    float dnm = 1.f;
    float acc[8];
    const float* hv = hbuf + (size_t)w * OUTC;
    #pragma unroll
    for (int k = 0; k < 8; k++) acc[k] = hv[k * 32 + lane];

    int beg = g_off[w], end = g_off[w + 1];
    for (int p = beg; p < end; p++) {
        int u = g_csrc[p];
        float e = leaky02(__ldg(als + u) + ad);
        float wg;
        if (e > m) {
            float s = __expf(m - e);
            dnm *= s;
            #pragma unroll
            for (int k = 0; k < 8; k++) acc[k] *= s;
            m = e;
            wg = 1.f;
        } else {
            wg = __expf(e - m);
        }
        dnm += wg;
        const float* hu = hbuf + (size_t)u * OUTC;
        #pragma unroll
        for (int k = 0; k < 8; k++)
            acc[k] += wg * __ldg(hu + k * 32 + lane);
    }
    float* ov = out + (size_t)w * OUTC;
    float inv = 1.f / dnm;
    #pragma unroll
    for (int k = 0; k < 8; k++) {
        int c = k * 32 + lane;
        ov[c] = acc[k] * inv + __ldg(bias + c);
    }
}

// ---------------- fp32 tiled GEMM: C = act(A[M,K] @ B[K,N] + bias) ----------
// BM=64, BN=64, BK=16, 256 threads, 4x4 per thread. N%64==0, K%16==0 required.
#define BM 64
#define BN 64
#define BK 16
__global__ __launch_bounds__(256) void k_gemm(const float* __restrict__ A,
                                              const float* __restrict__ B,
                                              const float* __restrict__ bias,
                                              float* __restrict__ C,
                                              int M, int K, int Nn, int act) {
    __shared__ float As[BK][BM + 4];
    __shared__ float Bs[BK][BN];
    int t = threadIdx.x;
    int tx = t & 15, ty = t >> 4;
    int row0 = blockIdx.y * BM;
    int col0 = blockIdx.x * BN;

    int arow = t >> 2, ak = (t & 3) * 4;          // A: 64 rows x 16 k, float4
    int brow = t >> 4, bcol = (t & 15) * 4;       // B: 16 rows x 64 n, float4
    bool arow_ok = (row0 + arow) < M;
    const float* Aptr = A + (size_t)(row0 + arow) * K + ak;
    const float* Bptr = B + (size_t)brow * Nn + col0 + bcol;

    float acc[4][4] = {};
    for (int k0 = 0; k0 < K; k0 += BK) {
        float4 av = arow_ok ? *(const float4*)(Aptr + k0)
                            : make_float4(0.f, 0.f, 0.f, 0.f);
        As[ak + 0][arow] = av.x; As[ak + 1][arow] = av.y;
        As[ak + 2][arow] = av.z; As[ak + 3][arow] = av.w;
        float4 bv = *(const float4*)(Bptr + (size_t)k0 * Nn);
        *(float4*)&Bs[brow][bcol] = bv;
        __syncthreads();
        #pragma unroll
        for (int kk = 0; kk < BK; kk++) {
            float4 a = *(const float4*)&As[kk][ty * 4];
            float4 b = *(const float4*)&Bs[kk][tx * 4];
            acc[0][0] += a.x * b.x; acc[0][1] += a.x * b.y; acc[0][2] += a.x * b.z; acc[0][3] += a.x * b.w;
            acc[1][0] += a.y * b.x; acc[1][1] += a.y * b.y; acc[1][2] += a.y * b.z; acc[1][3] += a.y * b.w;
            acc[2][0] += a.z * b.x; acc[2][1] += a.z * b.y; acc[2][2] += a.z * b.z; acc[2][3] += a.z * b.w;
            acc[3][0] += a.w * b.x; acc[3][1] += a.w * b.y; acc[3][2] += a.w * b.z; acc[3][3] += a.w * b.w;
        }
        __syncthreads();
    }
    #pragma unroll
    for (int i = 0; i < 4; i++) {
        int r = row0 + ty * 4 + i;
        if (r >= M) continue;
        #pragma unroll
        for (int j = 0; j < 4; j++) {
            int c = col0 + tx * 4 + j;
            float v = acc[i][j];
            if (bias) v += __ldg(bias + c);
            if (act == 1) v = v > 0.f ? v : 0.f;   // ReLU
            C[(size_t)r * Nn + c] = v;
        }
    }
}

// ---------------- launch ----------------------------------------------------
extern "C" void kernel_launch(void* const* d_in, const int* in_sizes, int n_in,
                              void* d_out, int out_size) {
    const float* x   = (const float*)d_in[0];
    const int*   ei  = (const int*)d_in[1];
    const float* W1  = (const float*)d_in[2];
    const float* as1 = (const float*)d_in[3];
    const float* ad1 = (const float*)d_in[4];
    const float* b1  = (const float*)d_in[5];
    const float* W2  = (const float*)d_in[6];
    const float* as2 = (const float*)d_in[7];
    const float* ad2 = (const float*)d_in[8];
    const float* b2  = (const float*)d_in[9];
    const float* W3  = (const float*)d_in[10];
    const float* as3 = (const float*)d_in[11];
    const float* ad3 = (const float*)d_in[12];
    const float* b3  = (const float*)d_in[13];
    const float* M1  = (const float*)d_in[14];
    const float* mb1 = (const float*)d_in[15];
    const float* M2  = (const float*)d_in[16];
    const float* mb2 = (const float*)d_in[17];
    const float* M3  = (const float*)d_in[18];
    const float* mb3 = (const float*)d_in[19];
    float* out = (float*)d_out;

    float *h, *feat, *als, *ald;
    cudaGetSymbolAddress((void**)&h,    g_h);
    cudaGetSymbolAddress((void**)&feat, g_feat);
    cudaGetSymbolAddress((void**)&als,  g_als);
    cudaGetSymbolAddress((void**)&ald,  g_ald);

    const int TB = 256;
    int nodeBlocks = (NN + TB - 1) / TB;
    int edgeBlocks = (EDGES + TB - 1) / TB;
    int warpBlocks = (NN * 32 + TB - 1) / TB;   // warp-per-node kernels

    // ---- CSR by dst ----
    k_zero_deg<<<nodeBlocks, TB>>>();
    k_count<<<edgeBlocks, TB>>>(ei);
    k_scan<<<1, 1024>>>();
    k_cursor_init<<<nodeBlocks, TB>>>();
    k_scatter<<<edgeBlocks, TB>>>(ei);

    dim3 gemmB(256);
    int mBlk = (NN + BM - 1) / BM;

    // ---- GAT layer 1: x[N,256] @ W1[256,512] ----
    k_gemm<<<dim3(CATC / BN, mBlk), gemmB>>>(x, W1, nullptr, h, NN, F_IN, CATC, 0);
    k_alpha4<<<warpBlocks, TB>>>(h, as1, ad1, als, ald);
    k_agg512<<<warpBlocks, TB>>>(h, als, ald, b1, feat);   // +b1, ELU

    // ---- GAT layer 2: feat[N,512] @ W2[512,512] ----
    k_gemm<<<dim3(CATC / BN, mBlk), gemmB>>>(feat, W2, nullptr, h, NN, CATC, CATC, 0);
    k_alpha4<<<warpBlocks, TB>>>(h, as2, ad2, als, ald);
    k_agg512<<<warpBlocks, TB>>>(h, als, ald, b2, feat);   // +b2, ELU

    // ---- GAT layer 3: feat[N,512] @ W3[512,256], 1 head, no concat/act ----
    k_gemm<<<dim3(OUTC / BN, mBlk), gemmB>>>(feat, W3, nullptr, h, NN, CATC, OUTC, 0);
    k_alpha1<<<warpBlocks, TB>>>(h, as3, ad3, als, ald);
    k_agg256<<<warpBlocks, TB>>>(h, als, ald, b3, feat);   // +b3

    // ---- MLP ----
    k_gemm<<<dim3(256 / BN, mBlk), gemmB>>>(feat, M1, mb1, h, NN, OUTC, 256, 1);      // ReLU
    k_gemm<<<dim3(128 / BN, mBlk), gemmB>>>(h, M2, mb2, feat, NN, 256, 128, 1);       // ReLU
    k_gemm<<<dim3(256 / BN, mBlk), gemmB>>>(feat, M3, mb3, out, NN, 128, 256, 0);     // linear
}

// round 7
// speedup vs baseline: 1.8171x; 1.8171x over previous
#include <cuda_runtime.h>
#include <cuda_bf16.h>
#include <cstdint>
#include <math.h>

// Problem constants (fixed by reference)
#define NN     50000
#define EDGES  800000
#define F_IN   256
#define HIDC   128
#define NHEAD  4
#define CATC   512   // NHEAD*HIDC
#define OUTC   256

// ---------------- device scratch (static globals; no allocation) ------------
__device__ float g_h[(size_t)NN * CATC];     // GEMM outputs per layer (102.4 MB)
__device__ float g_feat[(size_t)NN * CATC];  // aggregated/activated features (102.4 MB)
__device__ float g_als[NN * NHEAD];
__device__ float g_ald[NN * NHEAD];
__device__ int   g_deg[NN];
__device__ int   g_cur[NN];
__device__ int   g_off[NN + 1];
__device__ int   g_csrc[EDGES];

// ---------------- CSR build -------------------------------------------------
__global__ void k_zero_deg() {
    int i = blockIdx.x * blockDim.x + threadIdx.x;
    if (i < NN) g_deg[i] = 0;
}

__global__ void k_count(const int* __restrict__ ei) {
    int e = blockIdx.x * blockDim.x + threadIdx.x;
    if (e < EDGES) atomicAdd(&g_deg[ei[EDGES + e]], 1);
}

// single-block exclusive scan of g_deg -> g_off
__global__ void k_scan() {
    __shared__ int wsum[32];
    __shared__ int carry_s;
    int t = threadIdx.x;
    int lane = t & 31, wid = t >> 5;
    if (t == 0) carry_s = 0;
    __syncthreads();
    for (int base = 0; base < NN; base += 1024) {
        int i = base + t;
        int v = (i < NN) ? g_deg[i] : 0;
        int x = v;
        #pragma unroll
        for (int o = 1; o < 32; o <<= 1) {
            int y = __shfl_up_sync(0xFFFFFFFFu, x, o);
            if (lane >= o) x += y;
        }
        if (lane == 31) wsum[wid] = x;
        __syncthreads();
        if (wid == 0) {
            int ws = wsum[lane];
            #pragma unroll
            for (int o = 1; o < 32; o <<= 1) {
                int y = __shfl_up_sync(0xFFFFFFFFu, ws, o);
                if (lane >= o) ws += y;
            }
            wsum[lane] = ws;
        }
        __syncthreads();
        int incl = x + (wid ? wsum[wid - 1] : 0);
        int total = wsum[31];
        int carry = carry_s;
        if (i < NN) g_off[i] = carry + incl - v;   // exclusive
        __syncthreads();
        if (t == 0) carry_s = carry + total;
        __syncthreads();
    }
    if (t == 0) g_off[NN] = carry_s;
}

__global__ void k_cursor_init() {
    int i = blockIdx.x * blockDim.x + threadIdx.x;
    if (i < NN) g_cur[i] = g_off[i];
}

__global__ void k_scatter(const int* __restrict__ ei) {
    int e = blockIdx.x * blockDim.x + threadIdx.x;
    if (e < EDGES) {
        int s = ei[e], d = ei[EDGES + e];
        int p = atomicAdd(&g_cur[d], 1);
        g_csrc[p] = s;
    }
}

// ---------------- attention logit dot products ------------------------------
// warp per node, 512-ch / 4 heads
__global__ void k_alpha4(const float* __restrict__ hbuf,
                         const float* __restrict__ asrc,
                         const float* __restrict__ adst,
                         float* __restrict__ als, float* __restrict__ ald) {
    int w = (blockIdx.x * blockDim.x + threadIdx.x) >> 5;
    int lane = threadIdx.x & 31;
    if (w >= NN) return;
    const float* hv = hbuf + (size_t)w * CATC;
    float ps[4] = {0.f, 0.f, 0.f, 0.f}, pd[4] = {0.f, 0.f, 0.f, 0.f};
    #pragma unroll
    for (int k = 0; k < 16; k++) {
        int c = k * 32 + lane;
        float h = hv[c];
        int hh = k >> 2;
        int cc = (k & 3) * 32 + lane;
        ps[hh] += h * __ldg(asrc + hh * HIDC + cc);
        pd[hh] += h * __ldg(adst + hh * HIDC + cc);
    }
    #pragma unroll
    for (int hh = 0; hh < 4; hh++) {
        #pragma unroll
        for (int o = 16; o; o >>= 1) {
            ps[hh] += __shfl_xor_sync(0xFFFFFFFFu, ps[hh], o);
            pd[hh] += __shfl_xor_sync(0xFFFFFFFFu, pd[hh], o);
        }
    }
    if (lane == 0) {
        float4 s4 = make_float4(ps[0], ps[1], ps[2], ps[3]);
        float4 d4 = make_float4(pd[0], pd[1], pd[2], pd[3]);
        *(float4*)(als + 4 * w) = s4;
        *(float4*)(ald + 4 * w) = d4;
    }
}

// warp per node, 256-ch / 1 head
__global__ void k_alpha1(const float* __restrict__ hbuf,
                         const float* __restrict__ asrc,
                         const float* __restrict__ adst,
                         float* __restrict__ als, float* __restrict__ ald) {
    int w = (blockIdx.x * blockDim.x + threadIdx.x) >> 5;
    int lane = threadIdx.x & 31;
    if (w >= NN) return;
    const float* hv = hbuf + (size_t)w * OUTC;
    float ps = 0.f, pd = 0.f;
    #pragma unroll
    for (int k = 0; k < 8; k++) {
        int c = k * 32 + lane;
        float h = hv[c];
        ps += h * __ldg(asrc + c);
        pd += h * __ldg(adst + c);
    }
    #pragma unroll
    for (int o = 16; o; o >>= 1) {
        ps += __shfl_xor_sync(0xFFFFFFFFu, ps, o);
        pd += __shfl_xor_sync(0xFFFFFFFFu, pd, o);
    }
    if (lane == 0) { als[w] = ps; ald[w] = pd; }
}

__device__ __forceinline__ float leaky02(float x) { return x > 0.f ? x : 0.2f * x; }

// ---------------- per-dst segment softmax + weighted aggregation ------------
__global__ void k_agg512(const float* __restrict__ hbuf,
                         const float* __restrict__ als,
                         const float* __restrict__ ald,
                         const float* __restrict__ bias,
                         float* __restrict__ out) {
    int w = (blockIdx.x * blockDim.x + threadIdx.x) >> 5;
    int lane = threadIdx.x & 31;
    if (w >= NN) return;

    float4 adv = __ldg((const float4*)(ald + 4 * w));
    float ad[4] = {adv.x, adv.y, adv.z, adv.w};
    float4 asv = __ldg((const float4*)(als + 4 * w));
    float m[4], dnm[4], acc[16];
    m[0] = leaky02(asv.x + ad[0]); m[1] = leaky02(asv.y + ad[1]);
    m[2] = leaky02(asv.z + ad[2]); m[3] = leaky02(asv.w + ad[3]);
    dnm[0] = dnm[1] = dnm[2] = dnm[3] = 1.f;
    const float* hv = hbuf + (size_t)w * CATC;
    #pragma unroll
    for (int k = 0; k < 16; k++) acc[k] = hv[k * 32 + lane];

    int beg = g_off[w], end = g_off[w + 1];
    for (int p = beg; p < end; p++) {
        int u = g_csrc[p];
        float4 asu = __ldg((const float4*)(als + 4 * u));
        float ev[4] = {leaky02(asu.x + ad[0]), leaky02(asu.y + ad[1]),
                       leaky02(asu.z + ad[2]), leaky02(asu.w + ad[3])};
        float w4[4];
        #pragma unroll
        for (int hh = 0; hh < 4; hh++) {
            float e = ev[hh];
            if (e > m[hh]) {
                float s = __expf(m[hh] - e);
                dnm[hh] *= s;
                acc[4 * hh + 0] *= s; acc[4 * hh + 1] *= s;
                acc[4 * hh + 2] *= s; acc[4 * hh + 3] *= s;
                m[hh] = e;
                w4[hh] = 1.f;
            } else {
                w4[hh] = __expf(e - m[hh]);
            }
            dnm[hh] += w4[hh];
        }
        const float* hu = hbuf + (size_t)u * CATC;
        #pragma unroll
        for (int k = 0; k < 16; k++)
            acc[k] += w4[k >> 2] * __ldg(hu + k * 32 + lane);
    }
    float* ov = out + (size_t)w * CATC;
    #pragma unroll
    for (int k = 0; k < 16; k++) {
        int c = k * 32 + lane;
        float v = acc[k] / dnm[k >> 2] + __ldg(bias + c);
        v = v > 0.f ? v : (__expf(v) - 1.f);   // ELU
        ov[c] = v;
    }
}

__global__ void k_agg256(const float* __restrict__ hbuf,
                         const float* __restrict__ als,
                         const float* __restrict__ ald,
                         const float* __restrict__ bias,
                         float* __restrict__ out) {
    int w = (blockIdx.x * blockDim.x + threadIdx.x) >> 5;
    int lane = threadIdx.x & 31;
    if (w >= NN) return;

    float ad = __ldg(ald + w);
    float m = leaky02(__ldg(als + w) + ad);
    float dnm = 1.f;
    float acc[8];
    const float* hv = hbuf + (size_t)w * OUTC;
    #pragma unroll
    for (int k = 0; k < 8; k++) acc[k] = hv[k * 32 + lane];

    int beg = g_off[w], end = g_off[w + 1];
    for (int p = beg; p < end; p++) {
        int u = g_csrc[p];
        float e = leaky02(__ldg(als + u) + ad);
        float wg;
        if (e > m) {
            float s = __expf(m - e);
            dnm *= s;
            #pragma unroll
            for (int k = 0; k < 8; k++) acc[k] *= s;
            m = e;
            wg = 1.f;
        } else {
            wg = __expf(e - m);
        }
        dnm += wg;
        const float* hu = hbuf + (size_t)u * OUTC;
        #pragma unroll
        for (int k = 0; k < 8; k++)
            acc[k] += wg * __ldg(hu + k * 32 + lane);
    }
    float* ov = out + (size_t)w * OUTC;
    float inv = 1.f / dnm;
    #pragma unroll
    for (int k = 0; k < 8; k++) {
        int c = k * 32 + lane;
        ov[c] = acc[k] * inv + __ldg(bias + c);
    }
}

// ================= tf32 tensor-core GEMM =====================================
// C = act(A[M,K] @ B[K,N] + bias), tf32 inputs (cvt.rna), fp32 accumulate.
// Block 256x128x16, 8 warps (4m x 2n), warp tile 64x64 via mma.m16n8k8.
// Requires K % 16 == 0, N % 128 == 0. M guarded.
#define GBM 256
#define GBN 128
#define GBK 16
#define ASTR 20    // GBK + 4 pad (conflict-free A frag LDS, 16B-aligned rows)
#define BSTR 132   // GBN + 4 pad
#define GEMM_SMEM ((2 * GBM * ASTR + 2 * GBK * BSTR) * 4)

__device__ __forceinline__ uint32_t f2tf(float f) {
    uint32_t u;
    asm("cvt.rna.tf32.f32 %0, %1;" : "=r"(u) : "f"(f));
    return u;
}
__device__ __forceinline__ void cpa16(float* smem, const float* g, int sz) {
    uint32_t s = (uint32_t)__cvta_generic_to_shared(smem);
    asm volatile("cp.async.cg.shared.global [%0], [%1], 16, %2;\n"
                 :: "r"(s), "l"(g), "r"(sz));
}
__device__ __forceinline__ void cpcommit() { asm volatile("cp.async.commit_group;\n"); }
__device__ __forceinline__ void cpwait1()  { asm volatile("cp.async.wait_group 1;\n" ::: "memory"); }

__global__ void __launch_bounds__(256, 1)
k_gemm_tf32(const float* __restrict__ A, const float* __restrict__ B,
            const float* __restrict__ bias, float* __restrict__ C,
            int M, int K, int Nn, int act) {
    extern __shared__ float sm[];
    float* Asm = sm;                     // [2][GBM][ASTR]
    float* Bsm = sm + 2 * GBM * ASTR;    // [2][GBK][BSTR]
    int t = threadIdx.x;
    int lane = t & 31, wid = t >> 5;
    int grp = lane >> 2, kq = lane & 3;
    int wm0 = (wid >> 1) * 64;
    int wn0 = (wid & 1) * 64;
    int row0 = blockIdx.y * GBM;
    int col0 = blockIdx.x * GBN;

    float acc[4][8][4];
    #pragma unroll
    for (int i = 0; i < 4; i++)
        #pragma unroll
        for (int j = 0; j < 8; j++)
            #pragma unroll
            for (int q = 0; q < 4; q++) acc[i][j][q] = 0.f;

    // load coordinates: A tile = 256x16 floats -> 1024 16B chunks, 4/thread
    //                   B tile = 16x128 floats -> 512 chunks, 2/thread
    int aRow[4], aKc[4], bRow[2], bNc[2];
    #pragma unroll
    for (int i = 0; i < 4; i++) { int c = i * 256 + t; aRow[i] = c >> 2; aKc[i] = (c & 3) * 4; }
    #pragma unroll
    for (int i = 0; i < 2; i++) { int c = i * 256 + t; bRow[i] = c >> 5; bNc[i] = (c & 31) * 4; }

    auto loadTile = [&](int it, int buf) {
        int k0 = it * GBK;
        #pragma unroll
        for (int i = 0; i < 4; i++) {
            int r = row0 + aRow[i];
            int sz = (r < M) ? 16 : 0;
            const float* src = A + (size_t)(sz ? r : 0) * K + k0 + aKc[i];
            cpa16(Asm + buf * GBM * ASTR + aRow[i] * ASTR + aKc[i], src, sz);
        }
        #pragma unroll
        for (int i = 0; i < 2; i++) {
            const float* src = B + (size_t)(k0 + bRow[i]) * Nn + col0 + bNc[i];
            cpa16(Bsm + buf * GBK * BSTR + bRow[i] * BSTR + bNc[i], src, 16);
        }
    };

    int nIter = K / GBK;
    loadTile(0, 0);
    cpcommit();
    int buf = 0;
    for (int it = 0; it < nIter; ++it) {
        if (it + 1 < nIter) loadTile(it + 1, buf ^ 1);
        cpcommit();
        cpwait1();           // current tile's group complete
        __syncthreads();
        const float* Ab = Asm + buf * GBM * ASTR;
        const float* Bb = Bsm + buf * GBK * BSTR;
        #pragma unroll
        for (int s = 0; s < 2; ++s) {   // two k8 steps per 16-wide tile
            int kk = s * 8;
            uint32_t af[4][4], bf[8][2];
            #pragma unroll
            for (int mt = 0; mt < 4; mt++) {
                int m = wm0 + mt * 16 + grp;
                af[mt][0] = f2tf(Ab[(m)     * ASTR + kk + kq]);
                af[mt][1] = f2tf(Ab[(m + 8) * ASTR + kk + kq]);
                af[mt][2] = f2tf(Ab[(m)     * ASTR + kk + kq + 4]);
                af[mt][3] = f2tf(Ab[(m + 8) * ASTR + kk + kq + 4]);
            }
            #pragma unroll
            for (int nt = 0; nt < 8; nt++) {
                int n = wn0 + nt * 8 + grp;
                bf[nt][0] = f2tf(Bb[(kk + kq)     * BSTR + n]);
                bf[nt][1] = f2tf(Bb[(kk + kq + 4) * BSTR + n]);
            }
            #pragma unroll
            for (int mt = 0; mt < 4; mt++)
                #pragma unroll
                for (int nt = 0; nt < 8; nt++)
                    asm volatile(
                        "mma.sync.aligned.m16n8k8.row.col.f32.tf32.tf32.f32 "
                        "{%0,%1,%2,%3},{%4,%5,%6,%7},{%8,%9},{%0,%1,%2,%3};"
                        : "+f"(acc[mt][nt][0]), "+f"(acc[mt][nt][1]),
                          "+f"(acc[mt][nt][2]), "+f"(acc[mt][nt][3])
                        : "r"(af[mt][0]), "r"(af[mt][1]), "r"(af[mt][2]), "r"(af[mt][3]),
                          "r"(bf[nt][0]), "r"(bf[nt][1]));
        }
        __syncthreads();
        buf ^= 1;
    }

    // epilogue: c0,c1 -> row grp; c2,c3 -> row grp+8; cols 2*kq, 2*kq+1
    #pragma unroll
    for (int mt = 0; mt < 4; mt++) {
        #pragma unroll
        for (int half = 0; half < 2; half++) {
            int r = row0 + wm0 + mt * 16 + grp + half * 8;
            if (r < M) {
                #pragma unroll
                for (int nt = 0; nt < 8; nt++) {
                    int cix = col0 + wn0 + nt * 8 + 2 * kq;
                    float v0 = acc[mt][nt][half * 2 + 0];
                    float v1 = acc[mt][nt][half * 2 + 1];
                    if (bias) { v0 += __ldg(bias + cix); v1 += __ldg(bias + cix + 1); }
                    if (act)  { v0 = fmaxf(v0, 0.f); v1 = fmaxf(v1, 0.f); }
                    float2 vv = make_float2(v0, v1);
                    *(float2*)(C + (size_t)r * Nn + cix) = vv;
                }
            }
        }
    }
}

// ---------------- launch ----------------------------------------------------
extern "C" void kernel_launch(void* const* d_in, const int* in_sizes, int n_in,
                              void* d_out, int out_size) {
    const float* x   = (const float*)d_in[0];
    const int*   ei  = (const int*)d_in[1];
    const float* W1  = (const float*)d_in[2];
    const float* as1 = (const float*)d_in[3];
    const float* ad1 = (const float*)d_in[4];
    const float* b1  = (const float*)d_in[5];
    const float* W2  = (const float*)d_in[6];
    const float* as2 = (const float*)d_in[7];
    const float* ad2 = (const float*)d_in[8];
    const float* b2  = (const float*)d_in[9];
    const float* W3  = (const float*)d_in[10];
    const float* as3 = (const float*)d_in[11];
    const float* ad3 = (const float*)d_in[12];
    const float* b3  = (const float*)d_in[13];
    const float* M1  = (const float*)d_in[14];
    const float* mb1 = (const float*)d_in[15];
    const float* M2  = (const float*)d_in[16];
    const float* mb2 = (const float*)d_in[17];
    const float* M3  = (const float*)d_in[18];
    const float* mb3 = (const float*)d_in[19];
    float* out = (float*)d_out;

    float *h, *feat, *als, *ald;
    cudaGetSymbolAddress((void**)&h,    g_h);
    cudaGetSymbolAddress((void**)&feat, g_feat);
    cudaGetSymbolAddress((void**)&als,  g_als);
    cudaGetSymbolAddress((void**)&ald,  g_ald);

    static bool attr_done = false;
    if (!attr_done) {
        cudaFuncSetAttribute(k_gemm_tf32,
                             cudaFuncAttributeMaxDynamicSharedMemorySize, GEMM_SMEM);
        attr_done = true;
    }

    const int TB = 256;
    int nodeBlocks = (NN + TB - 1) / TB;
    int edgeBlocks = (EDGES + TB - 1) / TB;
    int warpBlocks = (NN * 32 + TB - 1) / TB;   // warp-per-node kernels

    // ---- CSR by dst ----
    k_zero_deg<<<nodeBlocks, TB>>>();
    k_count<<<edgeBlocks, TB>>>(ei);
    k_scan<<<1, 1024>>>();
    k_cursor_init<<<nodeBlocks, TB>>>();
    k_scatter<<<edgeBlocks, TB>>>(ei);

    int mBlk = (NN + GBM - 1) / GBM;   // 196

    // ---- GAT layer 1: x[N,256] @ W1[256,512] ----
    k_gemm_tf32<<<dim3(CATC / GBN, mBlk), 256, GEMM_SMEM>>>(x, W1, nullptr, h, NN, F_IN, CATC, 0);
    k_alpha4<<<warpBlocks, TB>>>(h, as1, ad1, als, ald);
    k_agg512<<<warpBlocks, TB>>>(h, als, ald, b1, feat);   // +b1, ELU

    // ---- GAT layer 2: feat[N,512] @ W2[512,512] ----
    k_gemm_tf32<<<dim3(CATC / GBN, mBlk), 256, GEMM_SMEM>>>(feat, W2, nullptr, h, NN, CATC, CATC, 0);
    k_alpha4<<<warpBlocks, TB>>>(h, as2, ad2, als, ald);
    k_agg512<<<warpBlocks, TB>>>(h, als, ald, b2, feat);   // +b2, ELU

    // ---- GAT layer 3: feat[N,512] @ W3[512,256], 1 head, no concat/act ----
    k_gemm_tf32<<<dim3(OUTC / GBN, mBlk), 256, GEMM_SMEM>>>(feat, W3, nullptr, h, NN, CATC, OUTC, 0);
    k_alpha1<<<warpBlocks, TB>>>(h, as3, ad3, als, ald);
    k_agg256<<<warpBlocks, TB>>>(h, als, ald, b3, feat);   // +b3

    // ---- MLP ----
    k_gemm_tf32<<<dim3(256 / GBN, mBlk), 256, GEMM_SMEM>>>(feat, M1, mb1, h, NN, OUTC, 256, 1);   // ReLU
    k_gemm_tf32<<<dim3(128 / GBN, mBlk), 256, GEMM_SMEM>>>(h, M2, mb2, feat, NN, 256, 128, 1);    // ReLU
    k_gemm_tf32<<<dim3(256 / GBN, mBlk), 256, GEMM_SMEM>>>(feat, M3, mb3, out, NN, 128, 256, 0);  // linear
}

// round 8
// speedup vs baseline: 2.2939x; 1.2624x over previous
#include <cuda_runtime.h>
#include <cuda_bf16.h>
#include <cstdint>
#include <math.h>

// Problem constants (fixed by reference)
#define NN     50000
#define EDGES  800000
#define F_IN   256
#define HIDC   128
#define NHEAD  4
#define CATC   512   // NHEAD*HIDC
#define OUTC   256

// ---------------- device scratch (static globals; no allocation) ------------
__device__ float g_h[(size_t)NN * CATC];     // GEMM outputs per layer (102.4 MB)
__device__ float g_feat[(size_t)NN * CATC];  // aggregated/activated features (102.4 MB)
__device__ float g_als[NN * NHEAD];
__device__ float g_ald[NN * NHEAD];
__device__ int   g_deg[NN];
__device__ int   g_cur[NN];
__device__ int   g_off[NN + 1];
__device__ int   g_csrc[EDGES];

// ---------------- CSR build -------------------------------------------------
__global__ void k_zero_deg() {
    int i = blockIdx.x * blockDim.x + threadIdx.x;
    if (i < NN) g_deg[i] = 0;
}

__global__ void k_count(const int* __restrict__ ei) {
    int e = blockIdx.x * blockDim.x + threadIdx.x;
    if (e < EDGES) atomicAdd(&g_deg[ei[EDGES + e]], 1);
}

// single-block exclusive scan of g_deg -> g_off
__global__ void k_scan() {
    __shared__ int wsum[32];
    __shared__ int carry_s;
    int t = threadIdx.x;
    int lane = t & 31, wid = t >> 5;
    if (t == 0) carry_s = 0;
    __syncthreads();
    for (int base = 0; base < NN; base += 1024) {
        int i = base + t;
        int v = (i < NN) ? g_deg[i] : 0;
        int x = v;
        #pragma unroll
        for (int o = 1; o < 32; o <<= 1) {
            int y = __shfl_up_sync(0xFFFFFFFFu, x, o);
            if (lane >= o) x += y;
        }
        if (lane == 31) wsum[wid] = x;
        __syncthreads();
        if (wid == 0) {
            int ws = wsum[lane];
            #pragma unroll
            for (int o = 1; o < 32; o <<= 1) {
                int y = __shfl_up_sync(0xFFFFFFFFu, ws, o);
                if (lane >= o) ws += y;
            }
            wsum[lane] = ws;
        }
        __syncthreads();
        int incl = x + (wid ? wsum[wid - 1] : 0);
        int total = wsum[31];
        int carry = carry_s;
        if (i < NN) g_off[i] = carry + incl - v;   // exclusive
        __syncthreads();
        if (t == 0) carry_s = carry + total;
        __syncthreads();
    }
    if (t == 0) g_off[NN] = carry_s;
}

__global__ void k_cursor_init() {
    int i = blockIdx.x * blockDim.x + threadIdx.x;
    if (i < NN) g_cur[i] = g_off[i];
}

__global__ void k_scatter(const int* __restrict__ ei) {
    int e = blockIdx.x * blockDim.x + threadIdx.x;
    if (e < EDGES) {
        int s = ei[e], d = ei[EDGES + e];
        int p = atomicAdd(&g_cur[d], 1);
        g_csrc[p] = s;
    }
}

// ---------------- attention logit dot products ------------------------------
// warp per node, 512-ch / 4 heads, float4 lanes
__global__ void k_alpha4(const float* __restrict__ hbuf,
                         const float* __restrict__ asrc,
                         const float* __restrict__ adst,
                         float* __restrict__ als, float* __restrict__ ald) {
    int w = (blockIdx.x * blockDim.x + threadIdx.x) >> 5;
    int lane = threadIdx.x & 31;
    if (w >= NN) return;
    const float4* hv = (const float4*)(hbuf + (size_t)w * CATC);
    float ps[4], pd[4];
    #pragma unroll
    for (int i = 0; i < 4; i++) {
        float4 h4 = hv[i * 32 + lane];
        float4 s4 = __ldg((const float4*)(asrc + i * HIDC) + lane);
        float4 d4 = __ldg((const float4*)(adst + i * HIDC) + lane);
        ps[i] = h4.x * s4.x + h4.y * s4.y + h4.z * s4.z + h4.w * s4.w;
        pd[i] = h4.x * d4.x + h4.y * d4.y + h4.z * d4.z + h4.w * d4.w;
    }
    #pragma unroll
    for (int hh = 0; hh < 4; hh++) {
        #pragma unroll
        for (int o = 16; o; o >>= 1) {
            ps[hh] += __shfl_xor_sync(0xFFFFFFFFu, ps[hh], o);
            pd[hh] += __shfl_xor_sync(0xFFFFFFFFu, pd[hh], o);
        }
    }
    if (lane == 0) {
        *(float4*)(als + 4 * w) = make_float4(ps[0], ps[1], ps[2], ps[3]);
        *(float4*)(ald + 4 * w) = make_float4(pd[0], pd[1], pd[2], pd[3]);
    }
}

// warp per node, 256-ch / 1 head
__global__ void k_alpha1(const float* __restrict__ hbuf,
                         const float* __restrict__ asrc,
                         const float* __restrict__ adst,
                         float* __restrict__ als, float* __restrict__ ald) {
    int w = (blockIdx.x * blockDim.x + threadIdx.x) >> 5;
    int lane = threadIdx.x & 31;
    if (w >= NN) return;
    const float4* hv = (const float4*)(hbuf + (size_t)w * OUTC);
    float ps = 0.f, pd = 0.f;
    #pragma unroll
    for (int i = 0; i < 2; i++) {
        float4 h4 = hv[i * 32 + lane];
        float4 s4 = __ldg((const float4*)(asrc + i * 128) + lane);
        float4 d4 = __ldg((const float4*)(adst + i * 128) + lane);
        ps += h4.x * s4.x + h4.y * s4.y + h4.z * s4.z + h4.w * s4.w;
        pd += h4.x * d4.x + h4.y * d4.y + h4.z * d4.z + h4.w * d4.w;
    }
    #pragma unroll
    for (int o = 16; o; o >>= 1) {
        ps += __shfl_xor_sync(0xFFFFFFFFu, ps, o);
        pd += __shfl_xor_sync(0xFFFFFFFFu, pd, o);
    }
    if (lane == 0) { als[w] = ps; ald[w] = pd; }
}

__device__ __forceinline__ float leaky02(float x) { return x > 0.f ? x : 0.2f * x; }

// ---------------- per-dst segment softmax + weighted aggregation ------------
// 4 heads x 128 ch; lane i-th float4 covers head i channels [4*lane..4*lane+3]
__global__ void k_agg512(const float* __restrict__ hbuf,
                         const float* __restrict__ als,
                         const float* __restrict__ ald,
                         const float* __restrict__ bias,
                         float* __restrict__ out) {
    int w = (blockIdx.x * blockDim.x + threadIdx.x) >> 5;
    int lane = threadIdx.x & 31;
    if (w >= NN) return;

    float4 adv = __ldg((const float4*)(ald + 4 * w));
    float ad[4] = {adv.x, adv.y, adv.z, adv.w};
    float4 asv = __ldg((const float4*)(als + 4 * w));
    float m[4], dnm[4];
    float4 acc4[4];
    // self loop seeds the online softmax (weight exp(0)=1)
    m[0] = leaky02(asv.x + ad[0]); m[1] = leaky02(asv.y + ad[1]);
    m[2] = leaky02(asv.z + ad[2]); m[3] = leaky02(asv.w + ad[3]);
    dnm[0] = dnm[1] = dnm[2] = dnm[3] = 1.f;
    const float4* hv = (const float4*)(hbuf + (size_t)w * CATC);
    #pragma unroll
    for (int i = 0; i < 4; i++) acc4[i] = hv[i * 32 + lane];

    int beg = g_off[w], end = g_off[w + 1];
    for (int p = beg; p < end; p++) {
        int u = g_csrc[p];
        float4 asu = __ldg((const float4*)(als + 4 * u));
        float ev[4] = {leaky02(asu.x + ad[0]), leaky02(asu.y + ad[1]),
                       leaky02(asu.z + ad[2]), leaky02(asu.w + ad[3])};
        float w4[4];
        #pragma unroll
        for (int hh = 0; hh < 4; hh++) {
            float e = ev[hh];
            if (e > m[hh]) {                       // warp-uniform branch
                float s = __expf(m[hh] - e);
                dnm[hh] *= s;
                acc4[hh].x *= s; acc4[hh].y *= s;
                acc4[hh].z *= s; acc4[hh].w *= s;
                m[hh] = e;
                w4[hh] = 1.f;
            } else {
                w4[hh] = __expf(e - m[hh]);
            }
            dnm[hh] += w4[hh];
        }
        const float4* hu = (const float4*)(hbuf + (size_t)u * CATC);
        #pragma unroll
        for (int i = 0; i < 4; i++) {
            float4 v = __ldg(hu + i * 32 + lane);
            float wi = w4[i];
            acc4[i].x += wi * v.x; acc4[i].y += wi * v.y;
            acc4[i].z += wi * v.z; acc4[i].w += wi * v.w;
        }
    }
    float4* ov = (float4*)(out + (size_t)w * CATC);
    #pragma unroll
    for (int i = 0; i < 4; i++) {
        float inv = 1.f / dnm[i];
        float4 b4 = __ldg((const float4*)(bias + i * 128) + lane);
        float4 v;
        v.x = acc4[i].x * inv + b4.x;
        v.y = acc4[i].y * inv + b4.y;
        v.z = acc4[i].z * inv + b4.z;
        v.w = acc4[i].w * inv + b4.w;
        v.x = v.x > 0.f ? v.x : (__expf(v.x) - 1.f);   // ELU
        v.y = v.y > 0.f ? v.y : (__expf(v.y) - 1.f);
        v.z = v.z > 0.f ? v.z : (__expf(v.z) - 1.f);
        v.w = v.w > 0.f ? v.w : (__expf(v.w) - 1.f);
        ov[i * 32 + lane] = v;
    }
}

// 1 head x 256 ch, warp per node; epilogue: +bias, no activation
__global__ void k_agg256(const float* __restrict__ hbuf,
                         const float* __restrict__ als,
                         const float* __restrict__ ald,
                         const float* __restrict__ bias,
                         float* __restrict__ out) {
    int w = (blockIdx.x * blockDim.x + threadIdx.x) >> 5;
    int lane = threadIdx.x & 31;
    if (w >= NN) return;

    float ad = __ldg(ald + w);
    float m = leaky02(__ldg(als + w) + ad);
    float dnm = 1.f;
    float4 acc4[2];
    const float4* hv = (const float4*)(hbuf + (size_t)w * OUTC);
    #pragma unroll
    for (int i = 0; i < 2; i++) acc4[i] = hv[i * 32 + lane];

    int beg = g_off[w], end = g_off[w + 1];
    for (int p = beg; p < end; p++) {
        int u = g_csrc[p];
        float e = leaky02(__ldg(als + u) + ad);
        float wg;
        if (e > m) {
            float s = __expf(m - e);
            dnm *= s;
            #pragma unroll
            for (int i = 0; i < 2; i++) {
                acc4[i].x *= s; acc4[i].y *= s; acc4[i].z *= s; acc4[i].w *= s;
            }
            m = e;
            wg = 1.f;
        } else {
            wg = __expf(e - m);
        }
        dnm += wg;
        const float4* hu = (const float4*)(hbuf + (size_t)u * OUTC);
        #pragma unroll
        for (int i = 0; i < 2; i++) {
            float4 v = __ldg(hu + i * 32 + lane);
            acc4[i].x += wg * v.x; acc4[i].y += wg * v.y;
            acc4[i].z += wg * v.z; acc4[i].w += wg * v.w;
        }
    }
    float4* ov = (float4*)(out + (size_t)w * OUTC);
    float inv = 1.f / dnm;
    #pragma unroll
    for (int i = 0; i < 2; i++) {
        float4 b4 = __ldg((const float4*)(bias + i * 128) + lane);
        float4 v;
        v.x = acc4[i].x * inv + b4.x;
        v.y = acc4[i].y * inv + b4.y;
        v.z = acc4[i].z * inv + b4.z;
        v.w = acc4[i].w * inv + b4.w;
        ov[i * 32 + lane] = v;
    }
}

// ================= fp16 tensor-core GEMM =====================================
// C = act(A[M,K] @ B[K,N] + bias). smem tiles stay fp32 (cp.async); fragments
// are packed to fp16 in registers (cvt.rn.f16x2.f32) -> mma.m16n8k16 fp32-acc.
// fp16 and tf32 share the 10-bit mantissa: same input-rounding error, 2x rate.
// Block 256x128x16, 8 warps (4m x 2n), warp tile 64x64. K%16==0, N%128==0.
#define GBM 256
#define GBN 128
#define GBK 16
#define ASTR 20    // GBK + 4 pad
#define BSTR 132   // GBN + 4 pad
#define GEMM_SMEM ((2 * GBM * ASTR + 2 * GBK * BSTR) * 4)

__device__ __forceinline__ uint32_t packh2(float lo, float hi) {
    uint32_t r;
    asm("cvt.rn.f16x2.f32 %0, %1, %2;" : "=r"(r) : "f"(hi), "f"(lo));  // %1->high, %2->low
    return r;
}
__device__ __forceinline__ void cpa16(float* smem, const float* g, int sz) {
    uint32_t s = (uint32_t)__cvta_generic_to_shared(smem);
    asm volatile("cp.async.cg.shared.global [%0], [%1], 16, %2;\n"
                 :: "r"(s), "l"(g), "r"(sz));
}
__device__ __forceinline__ void cpcommit() { asm volatile("cp.async.commit_group;\n"); }
__device__ __forceinline__ void cpwait1()  { asm volatile("cp.async.wait_group 1;\n" ::: "memory"); }

__global__ void __launch_bounds__(256, 1)
k_gemm_f16(const float* __restrict__ A, const float* __restrict__ B,
           const float* __restrict__ bias, float* __restrict__ C,
           int M, int K, int Nn, int act) {
    extern __shared__ float sm[];
    float* Asm = sm;                     // [2][GBM][ASTR]
    float* Bsm = sm + 2 * GBM * ASTR;    // [2][GBK][BSTR]
    int t = threadIdx.x;
    int lane = t & 31, wid = t >> 5;
    int grp = lane >> 2, kq = lane & 3;
    int wm0 = (wid >> 1) * 64;
    int wn0 = (wid & 1) * 64;
    int row0 = blockIdx.y * GBM;
    int col0 = blockIdx.x * GBN;

    float acc[4][8][4];
    #pragma unroll
    for (int i = 0; i < 4; i++)
        #pragma unroll
        for (int j = 0; j < 8; j++)
            #pragma unroll
            for (int q = 0; q < 4; q++) acc[i][j][q] = 0.f;

    // load coordinates: A tile = 256x16 floats -> 1024 16B chunks, 4/thread
    //                   B tile = 16x128 floats -> 512 chunks, 2/thread
    int aRow[4], aKc[4], bRow[2], bNc[2];
    #pragma unroll
    for (int i = 0; i < 4; i++) { int c = i * 256 + t; aRow[i] = c >> 2; aKc[i] = (c & 3) * 4; }
    #pragma unroll
    for (int i = 0; i < 2; i++) { int c = i * 256 + t; bRow[i] = c >> 5; bNc[i] = (c & 31) * 4; }

    auto loadTile = [&](int it, int buf) {
        int k0 = it * GBK;
        #pragma unroll
        for (int i = 0; i < 4; i++) {
            int r = row0 + aRow[i];
            int sz = (r < M) ? 16 : 0;
            const float* src = A + (size_t)(sz ? r : 0) * K + k0 + aKc[i];
            cpa16(Asm + buf * GBM * ASTR + aRow[i] * ASTR + aKc[i], src, sz);
        }
        #pragma unroll
        for (int i = 0; i < 2; i++) {
            const float* src = B + (size_t)(k0 + bRow[i]) * Nn + col0 + bNc[i];
            cpa16(Bsm + buf * GBK * BSTR + bRow[i] * BSTR + bNc[i], src, 16);
        }
    };

    int nIter = K / GBK;
    loadTile(0, 0);
    cpcommit();
    int buf = 0;
    for (int it = 0; it < nIter; ++it) {
        if (it + 1 < nIter) loadTile(it + 1, buf ^ 1);
        cpcommit();
        cpwait1();           // current tile's group complete
        __syncthreads();
        const float* Ab = Asm + buf * GBM * ASTR;
        const float* Bb = Bsm + buf * GBK * BSTR;

        // one m16n8k16 step covers the whole GBK=16 tile
        uint32_t af[4][4], bf[8][2];
        #pragma unroll
        for (int mt = 0; mt < 4; mt++) {
            int m = wm0 + mt * 16 + grp;
            const float* r0 = Ab + (size_t)m * ASTR;
            const float* r1 = Ab + (size_t)(m + 8) * ASTR;
            af[mt][0] = packh2(r0[2 * kq],     r0[2 * kq + 1]);   // rows grp,   k 2kq..
            af[mt][1] = packh2(r1[2 * kq],     r1[2 * kq + 1]);   // rows grp+8, k 2kq..
            af[mt][2] = packh2(r0[2 * kq + 8], r0[2 * kq + 9]);   // rows grp,   k 2kq+8..
            af[mt][3] = packh2(r1[2 * kq + 8], r1[2 * kq + 9]);   // rows grp+8, k 2kq+8..
        }
        #pragma unroll
        for (int nt = 0; nt < 8; nt++) {
            int n = wn0 + nt * 8 + grp;
            bf[nt][0] = packh2(Bb[(2 * kq) * BSTR + n],     Bb[(2 * kq + 1) * BSTR + n]);
            bf[nt][1] = packh2(Bb[(2 * kq + 8) * BSTR + n], Bb[(2 * kq + 9) * BSTR + n]);
        }
        #pragma unroll
        for (int mt = 0; mt < 4; mt++)
            #pragma unroll
            for (int nt = 0; nt < 8; nt++)
                asm volatile(
                    "mma.sync.aligned.m16n8k16.row.col.f32.f16.f16.f32 "
                    "{%0,%1,%2,%3},{%4,%5,%6,%7},{%8,%9},{%0,%1,%2,%3};"
                    : "+f"(acc[mt][nt][0]), "+f"(acc[mt][nt][1]),
                      "+f"(acc[mt][nt][2]), "+f"(acc[mt][nt][3])
                    : "r"(af[mt][0]), "r"(af[mt][1]), "r"(af[mt][2]), "r"(af[mt][3]),
                      "r"(bf[nt][0]), "r"(bf[nt][1]));
        __syncthreads();
        buf ^= 1;
    }

    // epilogue: c0,c1 -> row grp; c2,c3 -> row grp+8; cols 2*kq, 2*kq+1
    #pragma unroll
    for (int mt = 0; mt < 4; mt++) {
        #pragma unroll
        for (int half = 0; half < 2; half++) {
            int r = row0 + wm0 + mt * 16 + grp + half * 8;
            if (r < M) {
                #pragma unroll
                for (int nt = 0; nt < 8; nt++) {
                    int cix = col0 + wn0 + nt * 8 + 2 * kq;
                    float v0 = acc[mt][nt][half * 2 + 0];
                    float v1 = acc[mt][nt][half * 2 + 1];
                    if (bias) { v0 += __ldg(bias + cix); v1 += __ldg(bias + cix + 1); }
                    if (act)  { v0 = fmaxf(v0, 0.f); v1 = fmaxf(v1, 0.f); }
                    float2 vv = make_float2(v0, v1);
                    *(float2*)(C + (size_t)r * Nn + cix) = vv;
                }
            }
        }
    }
}

// ---------------- launch ----------------------------------------------------
extern "C" void kernel_launch(void* const* d_in, const int* in_sizes, int n_in,
                              void* d_out, int out_size) {
    const float* x   = (const float*)d_in[0];
    const int*   ei  = (const int*)d_in[1];
    const float* W1  = (const float*)d_in[2];
    const float* as1 = (const float*)d_in[3];
    const float* ad1 = (const float*)d_in[4];
    const float* b1  = (const float*)d_in[5];
    const float* W2  = (const float*)d_in[6];
    const float* as2 = (const float*)d_in[7];
    const float* ad2 = (const float*)d_in[8];
    const float* b2  = (const float*)d_in[9];
    const float* W3  = (const float*)d_in[10];
    const float* as3 = (const float*)d_in[11];
    const float* ad3 = (const float*)d_in[12];
    const float* b3  = (const float*)d_in[13];
    const float* M1  = (const float*)d_in[14];
    const float* mb1 = (const float*)d_in[15];
    const float* M2  = (const float*)d_in[16];
    const float* mb2 = (const float*)d_in[17];
    const float* M3  = (const float*)d_in[18];
    const float* mb3 = (const float*)d_in[19];
    float* out = (float*)d_out;

    float *h, *feat, *als, *ald;
    cudaGetSymbolAddress((void**)&h,    g_h);
    cudaGetSymbolAddress((void**)&feat, g_feat);
    cudaGetSymbolAddress((void**)&als,  g_als);
    cudaGetSymbolAddress((void**)&ald,  g_ald);

    static bool attr_done = false;
    if (!attr_done) {
        cudaFuncSetAttribute(k_gemm_f16,
                             cudaFuncAttributeMaxDynamicSharedMemorySize, GEMM_SMEM);
        attr_done = true;
    }

    const int TB = 256;
    int nodeBlocks = (NN + TB - 1) / TB;
    int edgeBlocks = (EDGES + TB - 1) / TB;
    int warpBlocks = (NN * 32 + TB - 1) / TB;   // warp-per-node kernels

    // ---- CSR by dst ----
    k_zero_deg<<<nodeBlocks, TB>>>();
    k_count<<<edgeBlocks, TB>>>(ei);
    k_scan<<<1, 1024>>>();
    k_cursor_init<<<nodeBlocks, TB>>>();
    k_scatter<<<edgeBlocks, TB>>>(ei);

    int mBlk = (NN + GBM - 1) / GBM;   // 196

    // ---- GAT layer 1: x[N,256] @ W1[256,512] ----
    k_gemm_f16<<<dim3(CATC / GBN, mBlk), 256, GEMM_SMEM>>>(x, W1, nullptr, h, NN, F_IN, CATC, 0);
    k_alpha4<<<warpBlocks, TB>>>(h, as1, ad1, als, ald);
    k_agg512<<<warpBlocks, TB>>>(h, als, ald, b1, feat);   // +b1, ELU

    // ---- GAT layer 2: feat[N,512] @ W2[512,512] ----
    k_gemm_f16<<<dim3(CATC / GBN, mBlk), 256, GEMM_SMEM>>>(feat, W2, nullptr, h, NN, CATC, CATC, 0);
    k_alpha4<<<warpBlocks, TB>>>(h, as2, ad2, als, ald);
    k_agg512<<<warpBlocks, TB>>>(h, als, ald, b2, feat);   // +b2, ELU

    // ---- GAT layer 3: feat[N,512] @ W3[512,256], 1 head, no concat/act ----
    k_gemm_f16<<<dim3(OUTC / GBN, mBlk), 256, GEMM_SMEM>>>(feat, W3, nullptr, h, NN, CATC, OUTC, 0);
    k_alpha1<<<warpBlocks, TB>>>(h, as3, ad3, als, ald);
    k_agg256<<<warpBlocks, TB>>>(h, als, ald, b3, feat);   // +b3

    // ---- MLP ----
    k_gemm_f16<<<dim3(256 / GBN, mBlk), 256, GEMM_SMEM>>>(feat, M1, mb1, h, NN, OUTC, 256, 1);   // ReLU
    k_gemm_f16<<<dim3(128 / GBN, mBlk), 256, GEMM_SMEM>>>(h, M2, mb2, feat, NN, 256, 128, 1);    // ReLU
    k_gemm_f16<<<dim3(256 / GBN, mBlk), 256, GEMM_SMEM>>>(feat, M3, mb3, out, NN, 128, 256, 0);  // linear
}

// round 9
// speedup vs baseline: 2.4920x; 1.0864x over previous
#include <cuda_runtime.h>
#include <cuda_fp16.h>
#include <cstdint>
#include <math.h>

// Problem constants (fixed by reference)
#define NN     50000
#define EDGES  800000
#define F_IN   256
#define HIDC   128
#define NHEAD  4
#define CATC   512   // NHEAD*HIDC
#define OUTC   256

// ---------------- device scratch (static globals; no allocation) ------------
__device__ __align__(16) __half g_h16[(size_t)NN * CATC];   // GEMM outputs (51.2 MB)
__device__ __align__(16) __half g_f16[(size_t)NN * CATC];   // aggregated feats (51.2 MB)
__device__ __align__(16) __half g_x16[(size_t)NN * F_IN];   // fp16 copy of x (25.6 MB)
__device__ __align__(16) __half g_w16[655360];              // fp16 transposed weights
__device__ float g_als[NN * NHEAD];
__device__ float g_ald[NN * NHEAD];
__device__ int   g_deg[NN];
__device__ int   g_cur[NN];
__device__ int   g_off[NN + 1];
__device__ int   g_csrc[EDGES];

// transposed-weight offsets inside g_w16
#define OFF_W1T 0
#define OFF_W2T 131072
#define OFF_W3T 393216
#define OFF_M1T 524288
#define OFF_M2T 589824
#define OFF_M3T 622592

// ---------------- conversion kernels ----------------------------------------
__global__ void k_cvt4(const float* __restrict__ src, __half* __restrict__ dst, int n4) {
    int i = blockIdx.x * blockDim.x + threadIdx.x;
    if (i < n4) {
        float4 v = ((const float4*)src)[i];
        __half2 a = __floats2half2_rn(v.x, v.y);
        __half2 b = __floats2half2_rn(v.z, v.w);
        ((__half2*)dst)[2 * i]     = a;
        ((__half2*)dst)[2 * i + 1] = b;
    }
}

// dst (fp16, [Nc][K] = W^T) from src (fp32, [K][Nc]); coalesced writes
__global__ void k_cvt_wT(const float* __restrict__ src, __half* __restrict__ dst,
                         int K, int Nc) {
    int id = blockIdx.x * blockDim.x + threadIdx.x;
    if (id < K * Nc) {
        int k = id % K, n = id / K;
        dst[id] = __float2half_rn(src[k * Nc + n]);
    }
}

// ---------------- CSR build -------------------------------------------------
__global__ void k_zero_deg() {
    int i = blockIdx.x * blockDim.x + threadIdx.x;
    if (i < NN) g_deg[i] = 0;
}

__global__ void k_count(const int* __restrict__ ei) {
    int e = blockIdx.x * blockDim.x + threadIdx.x;
    if (e < EDGES) atomicAdd(&g_deg[ei[EDGES + e]], 1);
}

__global__ void k_scan() {
    __shared__ int wsum[32];
    __shared__ int carry_s;
    int t = threadIdx.x;
    int lane = t & 31, wid = t >> 5;
    if (t == 0) carry_s = 0;
    __syncthreads();
    for (int base = 0; base < NN; base += 1024) {
        int i = base + t;
        int v = (i < NN) ? g_deg[i] : 0;
        int x = v;
        #pragma unroll
        for (int o = 1; o < 32; o <<= 1) {
            int y = __shfl_up_sync(0xFFFFFFFFu, x, o);
            if (lane >= o) x += y;
        }
        if (lane == 31) wsum[wid] = x;
        __syncthreads();
        if (wid == 0) {
            int ws = wsum[lane];
            #pragma unroll
            for (int o = 1; o < 32; o <<= 1) {
                int y = __shfl_up_sync(0xFFFFFFFFu, ws, o);
                if (lane >= o) ws += y;
            }
            wsum[lane] = ws;
        }
        __syncthreads();
        int incl = x + (wid ? wsum[wid - 1] : 0);
        int total = wsum[31];
        int carry = carry_s;
        if (i < NN) g_off[i] = carry + incl - v;
        __syncthreads();
        if (t == 0) carry_s = carry + total;
        __syncthreads();
    }
    if (t == 0) g_off[NN] = carry_s;
}

__global__ void k_cursor_init() {
    int i = blockIdx.x * blockDim.x + threadIdx.x;
    if (i < NN) g_cur[i] = g_off[i];
}

__global__ void k_scatter(const int* __restrict__ ei) {
    int e = blockIdx.x * blockDim.x + threadIdx.x;
    if (e < EDGES) {
        int s = ei[e], d = ei[EDGES + e];
        int p = atomicAdd(&g_cur[d], 1);
        g_csrc[p] = s;
    }
}

// ---------------- attention logit dot products (fp16 h) ---------------------
// chunk = 16B = 8 halves; row 512 halves = 64 chunks; chunk c -> head c>>4,
// channels 8*(c&15)..+7 within head.
__global__ void k_alpha4(const __half* __restrict__ hbuf,
                         const float* __restrict__ asrc,
                         const float* __restrict__ adst,
                         float* __restrict__ als, float* __restrict__ ald) {
    int w = (blockIdx.x * blockDim.x + threadIdx.x) >> 5;
    int lane = threadIdx.x & 31;
    if (w >= NN) return;
    const uint4* hv = (const uint4*)(hbuf + (size_t)w * CATC);
    float ps[4] = {0.f, 0.f, 0.f, 0.f}, pd[4] = {0.f, 0.f, 0.f, 0.f};
    #pragma unroll
    for (int j = 0; j < 2; j++) {
        int c = j * 32 + lane;
        uint4 q = hv[c];
        int hd = c >> 4;
        int base = 8 * (c & 15);
        const __half2* hp = (const __half2*)&q;
        float4 s0 = __ldg((const float4*)(asrc + hd * HIDC + base));
        float4 s1 = __ldg((const float4*)(asrc + hd * HIDC + base + 4));
        float4 d0 = __ldg((const float4*)(adst + hd * HIDC + base));
        float4 d1 = __ldg((const float4*)(adst + hd * HIDC + base + 4));
        float2 f0 = __half22float2(hp[0]);
        float2 f1 = __half22float2(hp[1]);
        float2 f2 = __half22float2(hp[2]);
        float2 f3 = __half22float2(hp[3]);
        ps[hd] += f0.x * s0.x + f0.y * s0.y + f1.x * s0.z + f1.y * s0.w
                + f2.x * s1.x + f2.y * s1.y + f3.x * s1.z + f3.y * s1.w;
        pd[hd] += f0.x * d0.x + f0.y * d0.y + f1.x * d0.z + f1.y * d0.w
                + f2.x * d1.x + f2.y * d1.y + f3.x * d1.z + f3.y * d1.w;
    }
    #pragma unroll
    for (int hh = 0; hh < 4; hh++) {
        #pragma unroll
        for (int o = 16; o; o >>= 1) {
            ps[hh] += __shfl_xor_sync(0xFFFFFFFFu, ps[hh], o);
            pd[hh] += __shfl_xor_sync(0xFFFFFFFFu, pd[hh], o);
        }
    }
    if (lane == 0) {
        *(float4*)(als + 4 * w) = make_float4(ps[0], ps[1], ps[2], ps[3]);
        *(float4*)(ald + 4 * w) = make_float4(pd[0], pd[1], pd[2], pd[3]);
    }
}

// 1 head x 256 ch; row = 32 chunks, lane -> chunk lane, channels 8*lane..
__global__ void k_alpha1(const __half* __restrict__ hbuf,
                         const float* __restrict__ asrc,
                         const float* __restrict__ adst,
                         float* __restrict__ als, float* __restrict__ ald) {
    int w = (blockIdx.x * blockDim.x + threadIdx.x) >> 5;
    int lane = threadIdx.x & 31;
    if (w >= NN) return;
    const uint4* hv = (const uint4*)(hbuf + (size_t)w * OUTC);
    uint4 q = hv[lane];
    const __half2* hp = (const __half2*)&q;
    int base = 8 * lane;
    float4 s0 = __ldg((const float4*)(asrc + base));
    float4 s1 = __ldg((const float4*)(asrc + base + 4));
    float4 d0 = __ldg((const float4*)(adst + base));
    float4 d1 = __ldg((const float4*)(adst + base + 4));
    float2 f0 = __half22float2(hp[0]);
    float2 f1 = __half22float2(hp[1]);
    float2 f2 = __half22float2(hp[2]);
    float2 f3 = __half22float2(hp[3]);
    float ps = f0.x * s0.x + f0.y * s0.y + f1.x * s0.z + f1.y * s0.w
             + f2.x * s1.x + f2.y * s1.y + f3.x * s1.z + f3.y * s1.w;
    float pd = f0.x * d0.x + f0.y * d0.y + f1.x * d0.z + f1.y * d0.w
             + f2.x * d1.x + f2.y * d1.y + f3.x * d1.z + f3.y * d1.w;
    #pragma unroll
    for (int o = 16; o; o >>= 1) {
        ps += __shfl_xor_sync(0xFFFFFFFFu, ps, o);
        pd += __shfl_xor_sync(0xFFFFFFFFu, pd, o);
    }
    if (lane == 0) { als[w] = ps; ald[w] = pd; }
}

__device__ __forceinline__ float leaky02(float x) { return x > 0.f ? x : 0.2f * x; }

__device__ __forceinline__ void unpack8(uint4 q, float* f) {
    const __half2* hp = (const __half2*)&q;
    float2 a = __half22float2(hp[0]); f[0] = a.x; f[1] = a.y;
    float2 b = __half22float2(hp[1]); f[2] = b.x; f[3] = b.y;
    float2 c = __half22float2(hp[2]); f[4] = c.x; f[5] = c.y;
    float2 d = __half22float2(hp[3]); f[6] = d.x; f[7] = d.y;
}

// ---------------- per-dst segment softmax + weighted aggregation ------------
// fp16 gathers, fp32 accumulators. Lane owns chunks lane (head lane>>4 in {0,1})
// and 32+lane (head in {2,3}). Online softmax: acc = acc*s[hd] + w[hd]*h.
__global__ void k_agg512(const __half* __restrict__ hbuf,
                         const float* __restrict__ als,
                         const float* __restrict__ ald,
                         const float* __restrict__ bias,
                         __half* __restrict__ out) {
    int w = (blockIdx.x * blockDim.x + threadIdx.x) >> 5;
    int lane = threadIdx.x & 31;
    if (w >= NN) return;

    float4 adv = __ldg((const float4*)(ald + 4 * w));
    float ad[4] = {adv.x, adv.y, adv.z, adv.w};
    float4 asv = __ldg((const float4*)(als + 4 * w));
    float m[4], dnm[4];
    m[0] = leaky02(asv.x + ad[0]); m[1] = leaky02(asv.y + ad[1]);
    m[2] = leaky02(asv.z + ad[2]); m[3] = leaky02(asv.w + ad[3]);
    dnm[0] = dnm[1] = dnm[2] = dnm[3] = 1.f;

    int c0 = lane, c1 = 32 + lane;
    int hd0 = c0 >> 4, hd1 = c1 >> 4;
    const uint4* hv = (const uint4*)(hbuf + (size_t)w * CATC);
    float acc0[8], acc1[8];
    unpack8(hv[c0], acc0);            // self loop seeds (weight 1)
    unpack8(hv[c1], acc1);

    int beg = g_off[w], end = g_off[w + 1];
    for (int p = beg; p < end; p++) {
        int u = g_csrc[p];
        float4 asu = __ldg((const float4*)(als + 4 * u));
        float ev[4] = {leaky02(asu.x + ad[0]), leaky02(asu.y + ad[1]),
                       leaky02(asu.z + ad[2]), leaky02(asu.w + ad[3])};
        float sh[4], wh[4];
        #pragma unroll
        for (int hh = 0; hh < 4; hh++) {
            float e = ev[hh];
            if (e > m[hh]) {                        // warp-uniform branch
                sh[hh] = __expf(m[hh] - e);
                wh[hh] = 1.f;
                m[hh] = e;
            } else {
                sh[hh] = 1.f;
                wh[hh] = __expf(e - m[hh]);
            }
            dnm[hh] = dnm[hh] * sh[hh] + wh[hh];
        }
        const uint4* hu = (const uint4*)(hbuf + (size_t)u * CATC);
        float v0[8], v1[8];
        unpack8(__ldg(hu + c0), v0);
        unpack8(__ldg(hu + c1), v1);
        float s0 = sh[hd0], w0 = wh[hd0];
        float s1 = sh[hd1], w1 = wh[hd1];
        #pragma unroll
        for (int e = 0; e < 8; e++) {
            acc0[e] = acc0[e] * s0 + w0 * v0[e];
            acc1[e] = acc1[e] * s1 + w1 * v1[e];
        }
    }

    uint4* ov = (uint4*)(out + (size_t)w * CATC);
    float inv0 = 1.f / dnm[hd0], inv1 = 1.f / dnm[hd1];
    {
        int base = 8 * c0;
        float4 b0 = __ldg((const float4*)(bias + base));
        float4 b1 = __ldg((const float4*)(bias + base + 4));
        float r[8];
        r[0] = acc0[0] * inv0 + b0.x; r[1] = acc0[1] * inv0 + b0.y;
        r[2] = acc0[2] * inv0 + b0.z; r[3] = acc0[3] * inv0 + b0.w;
        r[4] = acc0[4] * inv0 + b1.x; r[5] = acc0[5] * inv0 + b1.y;
        r[6] = acc0[6] * inv0 + b1.z; r[7] = acc0[7] * inv0 + b1.w;
        uint4 q;
        __half2* hp = (__half2*)&q;
        #pragma unroll
        for (int e = 0; e < 4; e++) {
            float x0 = r[2 * e], x1 = r[2 * e + 1];
            x0 = x0 > 0.f ? x0 : (__expf(x0) - 1.f);   // ELU
            x1 = x1 > 0.f ? x1 : (__expf(x1) - 1.f);
            hp[e] = __floats2half2_rn(x0, x1);
        }
        ov[c0] = q;
    }
    {
        int base = 8 * c1;
        float4 b0 = __ldg((const float4*)(bias + base));
        float4 b1 = __ldg((const float4*)(bias + base + 4));
        float r[8];
        r[0] = acc1[0] * inv1 + b0.x; r[1] = acc1[1] * inv1 + b0.y;
        r[2] = acc1[2] * inv1 + b0.z; r[3] = acc1[3] * inv1 + b0.w;
        r[4] = acc1[4] * inv1 + b1.x; r[5] = acc1[5] * inv1 + b1.y;
        r[6] = acc1[6] * inv1 + b1.z; r[7] = acc1[7] * inv1 + b1.w;
        uint4 q;
        __half2* hp = (__half2*)&q;
        #pragma unroll
        for (int e = 0; e < 4; e++) {
            float x0 = r[2 * e], x1 = r[2 * e + 1];
            x0 = x0 > 0.f ? x0 : (__expf(x0) - 1.f);
            x1 = x1 > 0.f ? x1 : (__expf(x1) - 1.f);
            hp[e] = __floats2half2_rn(x0, x1);
        }
        ov[c1] = q;
    }
}

// 1 head x 256 ch; lane -> chunk lane (channels 8*lane..); +bias, no act
__global__ void k_agg256(const __half* __restrict__ hbuf,
                         const float* __restrict__ als,
                         const float* __restrict__ ald,
                         const float* __restrict__ bias,
                         __half* __restrict__ out) {
    int w = (blockIdx.x * blockDim.x + threadIdx.x) >> 5;
    int lane = threadIdx.x & 31;
    if (w >= NN) return;

    float ad = __ldg(ald + w);
    float m = leaky02(__ldg(als + w) + ad);
    float dnm = 1.f;
    const uint4* hv = (const uint4*)(hbuf + (size_t)w * OUTC);
    float acc[8];
    unpack8(hv[lane], acc);

    int beg = g_off[w], end = g_off[w + 1];
    for (int p = beg; p < end; p++) {
        int u = g_csrc[p];
        float e = leaky02(__ldg(als + u) + ad);
        float sh, wh;
        if (e > m) {
            sh = __expf(m - e); wh = 1.f; m = e;
        } else {
            sh = 1.f; wh = __expf(e - m);
        }
        dnm = dnm * sh + wh;
        float v[8];
        unpack8(__ldg((const uint4*)(hbuf + (size_t)u * OUTC) + lane), v);
        #pragma unroll
        for (int e2 = 0; e2 < 8; e2++) acc[e2] = acc[e2] * sh + wh * v[e2];
    }
    float inv = 1.f / dnm;
    int base = 8 * lane;
    float4 b0 = __ldg((const float4*)(bias + base));
    float4 b1 = __ldg((const float4*)(bias + base + 4));
    float r[8];
    r[0] = acc[0] * inv + b0.x; r[1] = acc[1] * inv + b0.y;
    r[2] = acc[2] * inv + b0.z; r[3] = acc[3] * inv + b0.w;
    r[4] = acc[4] * inv + b1.x; r[5] = acc[5] * inv + b1.y;
    r[6] = acc[6] * inv + b1.z; r[7] = acc[7] * inv + b1.w;
    uint4 q;
    __half2* hp = (__half2*)&q;
    #pragma unroll
    for (int e2 = 0; e2 < 4; e2++)
        hp[e2] = __floats2half2_rn(r[2 * e2], r[2 * e2 + 1]);
    ((uint4*)(out + (size_t)w * OUTC))[lane] = q;
}

// ================= all-fp16 tensor-core GEMM =================================
// C = act(A[M,K] @ BT^T + bias); A fp16 row-major [M][K]; BT fp16 [N][K]
// (pre-transposed weights). smem fp16, fragments via single LDS.32, no CVT.
// Block 256x128x32, 8 warps (4m x 2n), warp tile 64x64, mma.m16n8k16.
#define GBM 256
#define GBN 128
#define GBK 32
#define AROW_U 20                 // uint32 per A smem row: 16 data + 4 pad (80B, 16B-aligned)
#define BROW_U 20
#define A_U (GBM * AROW_U)        // 5120 uint32 per stage
#define B_U (GBN * BROW_U)        // 2560 uint32 per stage
#define GEMM_SMEM ((2 * A_U + 2 * B_U) * 4)   // 61440 B

__device__ __forceinline__ void cpa16(uint32_t* smem, const __half* g, int sz) {
    uint32_t s = (uint32_t)__cvta_generic_to_shared(smem);
    asm volatile("cp.async.cg.shared.global [%0], [%1], 16, %2;\n"
                 :: "r"(s), "l"(g), "r"(sz));
}
__device__ __forceinline__ void cpcommit() { asm volatile("cp.async.commit_group;\n"); }
__device__ __forceinline__ void cpwait1()  { asm volatile("cp.async.wait_group 1;\n" ::: "memory"); }

__global__ void __launch_bounds__(256, 1)
k_gemm_h(const __half* __restrict__ A, const __half* __restrict__ BT,
         const float* __restrict__ bias, float* __restrict__ Cf,
         __half* __restrict__ Ch, int M, int K, int Nn, int act) {
    extern __shared__ uint32_t smu[];
    uint32_t* Asm = smu;                 // [2][GBM][AROW_U]
    uint32_t* Bsm = smu + 2 * A_U;       // [2][GBN][BROW_U]
    int t = threadIdx.x;
    int lane = t & 31, wid = t >> 5;
    int grp = lane >> 2, kq = lane & 3;
    int wm0 = (wid >> 1) * 64;
    int wn0 = (wid & 1) * 64;
    int row0 = blockIdx.y * GBM;
    int col0 = blockIdx.x * GBN;

    float acc[4][8][4];
    #pragma unroll
    for (int i = 0; i < 4; i++)
        #pragma unroll
        for (int j = 0; j < 8; j++)
            #pragma unroll
            for (int q = 0; q < 4; q++) acc[i][j][q] = 0.f;

    // A tile: 256 rows x 32 halves = 1024 16B-chunks -> 4/thread
    // B tile: 128 rows x 32 halves = 512 chunks -> 2/thread
    int aRow[4], aKo[4], bRow[2], bKo[2];
    #pragma unroll
    for (int i = 0; i < 4; i++) { int c = i * 256 + t; aRow[i] = c >> 2; aKo[i] = (c & 3) * 8; }
    #pragma unroll
    for (int i = 0; i < 2; i++) { int c = i * 256 + t; bRow[i] = c >> 2; bKo[i] = (c & 3) * 8; }

    auto loadTile = [&](int it, int buf) {
        int k0 = it * GBK;
        #pragma unroll
        for (int i = 0; i < 4; i++) {
            int r = row0 + aRow[i];
            int sz = (r < M) ? 16 : 0;
            const __half* src = A + (size_t)(sz ? r : 0) * K + k0 + aKo[i];
            cpa16(Asm + buf * A_U + aRow[i] * AROW_U + aKo[i] / 2, src, sz);
        }
        #pragma unroll
        for (int i = 0; i < 2; i++) {
            const __half* src = BT + (size_t)(col0 + bRow[i]) * K + k0 + bKo[i];
            cpa16(Bsm + buf * B_U + bRow[i] * BROW_U + bKo[i] / 2, src, 16);
        }
    };

    int nIter = K / GBK;
    loadTile(0, 0);
    cpcommit();
    int buf = 0;
    for (int it = 0; it < nIter; ++it) {
        if (it + 1 < nIter) loadTile(it + 1, buf ^ 1);
        cpcommit();
        cpwait1();
        __syncthreads();
        const uint32_t* Ab = Asm + buf * A_U;
        const uint32_t* Bb = Bsm + buf * B_U;
        #pragma unroll
        for (int s = 0; s < 2; ++s) {          // two m16n8k16 steps per k32 tile
            uint32_t af[4][4], bf[8][2];
            #pragma unroll
            for (int mt = 0; mt < 4; mt++) {
                int m = wm0 + mt * 16 + grp;
                const uint32_t* r0 = Ab + m * AROW_U + 8 * s;
                const uint32_t* r1 = r0 + 8 * AROW_U;
                af[mt][0] = r0[kq];
                af[mt][1] = r1[kq];
                af[mt][2] = r0[kq + 4];
                af[mt][3] = r1[kq + 4];
            }
            #pragma unroll
            for (int nt = 0; nt < 8; nt++) {
                int n = wn0 + nt * 8 + grp;
                const uint32_t* rb = Bb + n * BROW_U + 8 * s;
                bf[nt][0] = rb[kq];
                bf[nt][1] = rb[kq + 4];
            }
            #pragma unroll
            for (int mt = 0; mt < 4; mt++)
                #pragma unroll
                for (int nt = 0; nt < 8; nt++)
                    asm volatile(
                        "mma.sync.aligned.m16n8k16.row.col.f32.f16.f16.f32 "
                        "{%0,%1,%2,%3},{%4,%5,%6,%7},{%8,%9},{%0,%1,%2,%3};"
                        : "+f"(acc[mt][nt][0]), "+f"(acc[mt][nt][1]),
                          "+f"(acc[mt][nt][2]), "+f"(acc[mt][nt][3])
                        : "r"(af[mt][0]), "r"(af[mt][1]), "r"(af[mt][2]), "r"(af[mt][3]),
                          "r"(bf[nt][0]), "r"(bf[nt][1]));
        }
        __syncthreads();
        buf ^= 1;
    }

    // epilogue: c0,c1 -> row grp; c2,c3 -> row grp+8; cols 2*kq, 2*kq+1
    #pragma unroll
    for (int mt = 0; mt < 4; mt++) {
        #pragma unroll
        for (int half = 0; half < 2; half++) {
            int r = row0 + wm0 + mt * 16 + grp + half * 8;
            if (r < M) {
                #pragma unroll
                for (int nt = 0; nt < 8; nt++) {
                    int cix = col0 + wn0 + nt * 8 + 2 * kq;
                    float v0 = acc[mt][nt][half * 2 + 0];
                    float v1 = acc[mt][nt][half * 2 + 1];
                    if (bias) { v0 += __ldg(bias + cix); v1 += __ldg(bias + cix + 1); }
                    if (act)  { v0 = fmaxf(v0, 0.f); v1 = fmaxf(v1, 0.f); }
                    if (Ch) {
                        *(__half2*)(Ch + (size_t)r * Nn + cix) = __floats2half2_rn(v0, v1);
                    } else {
                        *(float2*)(Cf + (size_t)r * Nn + cix) = make_float2(v0, v1);
                    }
                }
            }
        }
    }
}

// ---------------- launch ----------------------------------------------------
extern "C" void kernel_launch(void* const* d_in, const int* in_sizes, int n_in,
                              void* d_out, int out_size) {
    const float* x   = (const float*)d_in[0];
    const int*   ei  = (const int*)d_in[1];
    const float* W1  = (const float*)d_in[2];
    const float* as1 = (const float*)d_in[3];
    const float* ad1 = (const float*)d_in[4];
    const float* b1  = (const float*)d_in[5];
    const float* W2  = (const float*)d_in[6];
    const float* as2 = (const float*)d_in[7];
    const float* ad2 = (const float*)d_in[8];
    const float* b2  = (const float*)d_in[9];
    const float* W3  = (const float*)d_in[10];
    const float* as3 = (const float*)d_in[11];
    const float* ad3 = (const float*)d_in[12];
    const float* b3  = (const float*)d_in[13];
    const float* M1  = (const float*)d_in[14];
    const float* mb1 = (const float*)d_in[15];
    const float* M2  = (const float*)d_in[16];
    const float* mb2 = (const float*)d_in[17];
    const float* M3  = (const float*)d_in[18];
    const float* mb3 = (const float*)d_in[19];
    float* out = (float*)d_out;

    __half *h16, *f16, *x16, *w16;
    float *als, *ald;
    cudaGetSymbolAddress((void**)&h16, g_h16);
    cudaGetSymbolAddress((void**)&f16, g_f16);
    cudaGetSymbolAddress((void**)&x16, g_x16);
    cudaGetSymbolAddress((void**)&w16, g_w16);
    cudaGetSymbolAddress((void**)&als, g_als);
    cudaGetSymbolAddress((void**)&ald, g_ald);

    static bool attr_done = false;
    if (!attr_done) {
        cudaFuncSetAttribute(k_gemm_h,
                             cudaFuncAttributeMaxDynamicSharedMemorySize, GEMM_SMEM);
        attr_done = true;
    }

    const int TB = 256;
    int nodeBlocks = (NN + TB - 1) / TB;
    int edgeBlocks = (EDGES + TB - 1) / TB;
    int warpBlocks = (NN * 32 + TB - 1) / TB;

    // ---- fp16 conversions: x and transposed weights ----
    int xn4 = NN * F_IN / 4;
    k_cvt4<<<(xn4 + TB - 1) / TB, TB>>>(x, x16, xn4);
    k_cvt_wT<<<(256 * 512 + TB - 1) / TB, TB>>>(W1, w16 + OFF_W1T, 256, 512);
    k_cvt_wT<<<(512 * 512 + TB - 1) / TB, TB>>>(W2, w16 + OFF_W2T, 512, 512);
    k_cvt_wT<<<(512 * 256 + TB - 1) / TB, TB>>>(W3, w16 + OFF_W3T, 512, 256);
    k_cvt_wT<<<(256 * 256 + TB - 1) / TB, TB>>>(M1, w16 + OFF_M1T, 256, 256);
    k_cvt_wT<<<(256 * 128 + TB - 1) / TB, TB>>>(M2, w16 + OFF_M2T, 256, 128);
    k_cvt_wT<<<(128 * 256 + TB - 1) / TB, TB>>>(M3, w16 + OFF_M3T, 128, 256);

    // ---- CSR by dst ----
    k_zero_deg<<<nodeBlocks, TB>>>();
    k_count<<<edgeBlocks, TB>>>(ei);
    k_scan<<<1, 1024>>>();
    k_cursor_init<<<nodeBlocks, TB>>>();
    k_scatter<<<edgeBlocks, TB>>>(ei);

    int mBlk = (NN + GBM - 1) / GBM;   // 196

    // ---- GAT layer 1: x16[N,256] @ W1 -> h16[N,512] ----
    k_gemm_h<<<dim3(CATC / GBN, mBlk), 256, GEMM_SMEM>>>(
        x16, w16 + OFF_W1T, nullptr, nullptr, h16, NN, F_IN, CATC, 0);
    k_alpha4<<<warpBlocks, TB>>>(h16, as1, ad1, als, ald);
    k_agg512<<<warpBlocks, TB>>>(h16, als, ald, b1, f16);   // +b1, ELU

    // ---- GAT layer 2: f16[N,512] @ W2 -> h16[N,512] ----
    k_gemm_h<<<dim3(CATC / GBN, mBlk), 256, GEMM_SMEM>>>(
        f16, w16 + OFF_W2T, nullptr, nullptr, h16, NN, CATC, CATC, 0);
    k_alpha4<<<warpBlocks, TB>>>(h16, as2, ad2, als, ald);
    k_agg512<<<warpBlocks, TB>>>(h16, als, ald, b2, f16);   // +b2, ELU

    // ---- GAT layer 3: f16[N,512] @ W3 -> h16[N,256], 1 head ----
    k_gemm_h<<<dim3(OUTC / GBN, mBlk), 256, GEMM_SMEM>>>(
        f16, w16 + OFF_W3T, nullptr, nullptr, h16, NN, CATC, OUTC, 0);
    k_alpha1<<<warpBlocks, TB>>>(h16, as3, ad3, als, ald);
    k_agg256<<<warpBlocks, TB>>>(h16, als, ald, b3, f16);   // +b3 (rows: 256 halves)

    // ---- MLP ----
    k_gemm_h<<<dim3(256 / GBN, mBlk), 256, GEMM_SMEM>>>(
        f16, w16 + OFF_M1T, mb1, nullptr, h16, NN, 256, 256, 1);   // ReLU
    k_gemm_h<<<dim3(128 / GBN, mBlk), 256, GEMM_SMEM>>>(
        h16, w16 + OFF_M2T, mb2, nullptr, f16, NN, 256, 128, 1);   // ReLU
    k_gemm_h<<<dim3(256 / GBN, mBlk), 256, GEMM_SMEM>>>(
        f16, w16 + OFF_M3T, mb3, out, nullptr, NN, 128, 256, 0);   // fp32 out
}

// round 12
// speedup vs baseline: 2.5761x; 1.0337x over previous
#include <cuda_runtime.h>
#include <cuda_fp16.h>
#include <cstdint>
#include <math.h>

// Problem constants (fixed by reference)
#define NN     50000
#define EDGES  800000
#define F_IN   256
#define HIDC   128
#define NHEAD  4
#define CATC   512   // NHEAD*HIDC
#define OUTC   256

// ---------------- device scratch (static globals; no allocation) ------------
__device__ __align__(16) __half g_h16[(size_t)NN * CATC];   // GEMM outputs (51.2 MB)
__device__ __align__(16) __half g_f16[(size_t)NN * CATC];   // aggregated feats (51.2 MB)
__device__ __align__(16) __half g_x16[(size_t)NN * F_IN];   // fp16 copy of x (25.6 MB)
__device__ __align__(16) __half g_w16[655360];              // fp16 transposed weights
__device__ float g_als[NN * NHEAD];
__device__ float g_ald[NN * NHEAD];
__device__ int   g_deg[NN];
__device__ int   g_cur[NN];
__device__ int   g_off[NN + 1];
__device__ int   g_csrc[EDGES];

// transposed-weight offsets inside g_w16
#define OFF_W1T 0
#define OFF_W2T 131072
#define OFF_W3T 393216
#define OFF_M1T 524288
#define OFF_M2T 589824
#define OFF_M3T 622592

// ---------------- conversion kernels ----------------------------------------
__global__ void k_cvt4(const float* __restrict__ src, __half* __restrict__ dst, int n4) {
    int i = blockIdx.x * blockDim.x + threadIdx.x;
    if (i < n4) {
        float4 v = ((const float4*)src)[i];
        ((__half2*)dst)[2 * i]     = __floats2half2_rn(v.x, v.y);
        ((__half2*)dst)[2 * i + 1] = __floats2half2_rn(v.z, v.w);
    }
}

// dst (fp16, [Nc][K] = W^T) from src (fp32, [K][Nc]); coalesced writes
__global__ void k_cvt_wT(const float* __restrict__ src, __half* __restrict__ dst,
                         int K, int Nc) {
    int id = blockIdx.x * blockDim.x + threadIdx.x;
    if (id < K * Nc) {
        int k = id % K, n = id / K;
        dst[id] = __float2half_rn(src[k * Nc + n]);
    }
}

// ---------------- CSR build -------------------------------------------------
__global__ void k_zero_deg() {
    int i = blockIdx.x * blockDim.x + threadIdx.x;
    if (i < NN) g_deg[i] = 0;
}

__global__ void k_count(const int* __restrict__ ei) {
    int e = blockIdx.x * blockDim.x + threadIdx.x;
    if (e < EDGES) atomicAdd(&g_deg[ei[EDGES + e]], 1);
}

// exclusive scan of g_deg -> g_off; also initializes g_cur = g_off
__global__ void k_scan() {
    __shared__ int wsum[32];
    __shared__ int carry_s;
    int t = threadIdx.x;
    int lane = t & 31, wid = t >> 5;
    if (t == 0) carry_s = 0;
    __syncthreads();
    for (int base = 0; base < NN; base += 1024) {
        int i = base + t;
        int v = (i < NN) ? g_deg[i] : 0;
        int x = v;
        #pragma unroll
        for (int o = 1; o < 32; o <<= 1) {
            int y = __shfl_up_sync(0xFFFFFFFFu, x, o);
            if (lane >= o) x += y;
        }
        if (lane == 31) wsum[wid] = x;
        __syncthreads();
        if (wid == 0) {
            int ws = wsum[lane];
            #pragma unroll
            for (int o = 1; o < 32; o <<= 1) {
                int y = __shfl_up_sync(0xFFFFFFFFu, ws, o);
                if (lane >= o) ws += y;
            }
            wsum[lane] = ws;
        }
        __syncthreads();
        int incl = x + (wid ? wsum[wid - 1] : 0);
        int total = wsum[31];
        int carry = carry_s;
        if (i < NN) {
            int off = carry + incl - v;
            g_off[i] = off;
            g_cur[i] = off;
        }
        __syncthreads();
        if (t == 0) carry_s = carry + total;
        __syncthreads();
    }
    if (t == 0) g_off[NN] = carry_s;
}

__global__ void k_scatter(const int* __restrict__ ei) {
    int e = blockIdx.x * blockDim.x + threadIdx.x;
    if (e < EDGES) {
        int s = ei[e], d = ei[EDGES + e];
        int p = atomicAdd(&g_cur[d], 1);
        g_csrc[p] = s;
    }
}

// ---------------- attention logit dot products (fp16 h) ---------------------
__global__ void k_alpha4(const __half* __restrict__ hbuf,
                         const float* __restrict__ asrc,
                         const float* __restrict__ adst,
                         float* __restrict__ als, float* __restrict__ ald) {
    int w = (blockIdx.x * blockDim.x + threadIdx.x) >> 5;
    int lane = threadIdx.x & 31;
    if (w >= NN) return;
    const uint4* hv = (const uint4*)(hbuf + (size_t)w * CATC);
    float ps[4] = {0.f, 0.f, 0.f, 0.f}, pd[4] = {0.f, 0.f, 0.f, 0.f};
    #pragma unroll
    for (int j = 0; j < 2; j++) {
        int c = j * 32 + lane;
        uint4 q = hv[c];
        int hd = c >> 4;
        int base = 8 * (c & 15);
        const __half2* hp = (const __half2*)&q;
        float4 s0 = __ldg((const float4*)(asrc + hd * HIDC + base));
        float4 s1 = __ldg((const float4*)(asrc + hd * HIDC + base + 4));
        float4 d0 = __ldg((const float4*)(adst + hd * HIDC + base));
        float4 d1 = __ldg((const float4*)(adst + hd * HIDC + base + 4));
        float2 f0 = __half22float2(hp[0]);
        float2 f1 = __half22float2(hp[1]);
        float2 f2 = __half22float2(hp[2]);
        float2 f3 = __half22float2(hp[3]);
        ps[hd] += f0.x * s0.x + f0.y * s0.y + f1.x * s0.z + f1.y * s0.w
                + f2.x * s1.x + f2.y * s1.y + f3.x * s1.z + f3.y * s1.w;
        pd[hd] += f0.x * d0.x + f0.y * d0.y + f1.x * d0.z + f1.y * d0.w
                + f2.x * d1.x + f2.y * d1.y + f3.x * d1.z + f3.y * d1.w;
    }
    #pragma unroll
    for (int hh = 0; hh < 4; hh++) {
        #pragma unroll
        for (int o = 16; o; o >>= 1) {
            ps[hh] += __shfl_xor_sync(0xFFFFFFFFu, ps[hh], o);
            pd[hh] += __shfl_xor_sync(0xFFFFFFFFu, pd[hh], o);
        }
    }
    if (lane == 0) {
        *(float4*)(als + 4 * w) = make_float4(ps[0], ps[1], ps[2], ps[3]);
        *(float4*)(ald + 4 * w) = make_float4(pd[0], pd[1], pd[2], pd[3]);
    }
}

__global__ void k_alpha1(const __half* __restrict__ hbuf,
                         const float* __restrict__ asrc,
                         const float* __restrict__ adst,
                         float* __restrict__ als, float* __restrict__ ald) {
    int w = (blockIdx.x * blockDim.x + threadIdx.x) >> 5;
    int lane = threadIdx.x & 31;
    if (w >= NN) return;
    const uint4* hv = (const uint4*)(hbuf + (size_t)w * OUTC);
    uint4 q = hv[lane];
    const __half2* hp = (const __half2*)&q;
    int base = 8 * lane;
    float4 s0 = __ldg((const float4*)(asrc + base));
    float4 s1 = __ldg((const float4*)(asrc + base + 4));
    float4 d0 = __ldg((const float4*)(adst + base));
    float4 d1 = __ldg((const float4*)(adst + base + 4));
    float2 f0 = __half22float2(hp[0]);
    float2 f1 = __half22float2(hp[1]);
    float2 f2 = __half22float2(hp[2]);
    float2 f3 = __half22float2(hp[3]);
    float ps = f0.x * s0.x + f0.y * s0.y + f1.x * s0.z + f1.y * s0.w
             + f2.x * s1.x + f2.y * s1.y + f3.x * s1.z + f3.y * s1.w;
    float pd = f0.x * d0.x + f0.y * d0.y + f1.x * d0.z + f1.y * d0.w
             + f2.x * d1.x + f2.y * d1.y + f3.x * d1.z + f3.y * d1.w;
    #pragma unroll
    for (int o = 16; o; o >>= 1) {
        ps += __shfl_xor_sync(0xFFFFFFFFu, ps, o);
        pd += __shfl_xor_sync(0xFFFFFFFFu, pd, o);
    }
    if (lane == 0) { als[w] = ps; ald[w] = pd; }
}

__device__ __forceinline__ float leaky02(float x) { return x > 0.f ? x : 0.2f * x; }

__device__ __forceinline__ void unpack8(uint4 q, float* f) {
    const __half2* hp = (const __half2*)&q;
    float2 a = __half22float2(hp[0]); f[0] = a.x; f[1] = a.y;
    float2 b = __half22float2(hp[1]); f[2] = b.x; f[3] = b.y;
    float2 c = __half22float2(hp[2]); f[4] = c.x; f[5] = c.y;
    float2 d = __half22float2(hp[3]); f[6] = d.x; f[7] = d.y;
}

// ---------------- per-dst segment softmax + weighted aggregation ------------
// Software-pipelined: edge p+1's csrc/als/h loads issue before edge p's math.
__global__ void k_agg512(const __half* __restrict__ hbuf,
                         const float* __restrict__ als,
                         const float* __restrict__ ald,
                         const float* __restrict__ bias,
                         __half* __restrict__ out) {
    int w = (blockIdx.x * blockDim.x + threadIdx.x) >> 5;
    int lane = threadIdx.x & 31;
    if (w >= NN) return;

    float4 adv = __ldg((const float4*)(ald + 4 * w));
    float ad[4] = {adv.x, adv.y, adv.z, adv.w};
    float4 asv = __ldg((const float4*)(als + 4 * w));
    float m[4], dnm[4];
    m[0] = leaky02(asv.x + ad[0]); m[1] = leaky02(asv.y + ad[1]);
    m[2] = leaky02(asv.z + ad[2]); m[3] = leaky02(asv.w + ad[3]);
    dnm[0] = dnm[1] = dnm[2] = dnm[3] = 1.f;

    int c0 = lane, c1 = 32 + lane;
    int hd0 = c0 >> 4, hd1 = c1 >> 4;
    const uint4* hv = (const uint4*)(hbuf + (size_t)w * CATC);
    float acc0[8], acc1[8];
    unpack8(hv[c0], acc0);            // self loop seeds (weight 1)
    unpack8(hv[c1], acc1);

    int beg = g_off[w], end = g_off[w + 1];
    if (beg < end) {
        // prime the pipeline with edge `beg`
        int u1 = g_csrc[beg];
        float4 a1 = __ldg((const float4*)(als + 4 * u1));
        const uint4* hu1 = (const uint4*)(hbuf + (size_t)u1 * CATC);
        uint4 q1a = __ldg(hu1 + c0);
        uint4 q1b = __ldg(hu1 + c1);

        for (int p = beg; p < end; p++) {
            // issue next edge's loads before doing this edge's math
            int pn = (p + 1 < end) ? p + 1 : p;
            int u2 = g_csrc[pn];
            float4 a2 = __ldg((const float4*)(als + 4 * u2));
            const uint4* hu2 = (const uint4*)(hbuf + (size_t)u2 * CATC);
            uint4 q2a = __ldg(hu2 + c0);
            uint4 q2b = __ldg(hu2 + c1);

            float ev[4] = {leaky02(a1.x + ad[0]), leaky02(a1.y + ad[1]),
                           leaky02(a1.z + ad[2]), leaky02(a1.w + ad[3])};
            float sh[4], wh[4];
            #pragma unroll
            for (int hh = 0; hh < 4; hh++) {
                float e = ev[hh];
                if (e > m[hh]) {                        // warp-uniform branch
                    sh[hh] = __expf(m[hh] - e);
                    wh[hh] = 1.f;
                    m[hh] = e;
                } else {
                    sh[hh] = 1.f;
                    wh[hh] = __expf(e - m[hh]);
                }
                dnm[hh] = dnm[hh] * sh[hh] + wh[hh];
            }
            float v0[8], v1[8];
            unpack8(q1a, v0);
            unpack8(q1b, v1);
            float s0 = sh[hd0], w0 = wh[hd0];
            float s1 = sh[hd1], w1 = wh[hd1];
            #pragma unroll
            for (int e = 0; e < 8; e++) {
                acc0[e] = acc0[e] * s0 + w0 * v0[e];
                acc1[e] = acc1[e] * s1 + w1 * v1[e];
            }
            a1 = a2; q1a = q2a; q1b = q2b;
        }
    }

    uint4* ov = (uint4*)(out + (size_t)w * CATC);
    float inv0 = 1.f / dnm[hd0], inv1 = 1.f / dnm[hd1];
    {
        int base = 8 * c0;
        float4 b0 = __ldg((const float4*)(bias + base));
        float4 b1 = __ldg((const float4*)(bias + base + 4));
        float r[8];
        r[0] = acc0[0] * inv0 + b0.x; r[1] = acc0[1] * inv0 + b0.y;
        r[2] = acc0[2] * inv0 + b0.z; r[3] = acc0[3] * inv0 + b0.w;
        r[4] = acc0[4] * inv0 + b1.x; r[5] = acc0[5] * inv0 + b1.y;
        r[6] = acc0[6] * inv0 + b1.z; r[7] = acc0[7] * inv0 + b1.w;
        uint4 q;
        __half2* hp = (__half2*)&q;
        #pragma unroll
        for (int e = 0; e < 4; e++) {
            float x0 = r[2 * e], x1 = r[2 * e + 1];
            x0 = x0 > 0.f ? x0 : (__expf(x0) - 1.f);   // ELU
            x1 = x1 > 0.f ? x1 : (__expf(x1) - 1.f);
            hp[e] = __floats2half2_rn(x0, x1);
        }
        ov[c0] = q;
    }
    {
        int base = 8 * c1;
        float4 b0 = __ldg((const float4*)(bias + base));
        float4 b1 = __ldg((const float4*)(bias + base + 4));
        float r[8];
        r[0] = acc1[0] * inv1 + b0.x; r[1] = acc1[1] * inv1 + b0.y;
        r[2] = acc1[2] * inv1 + b0.z; r[3] = acc1[3] * inv1 + b0.w;
        r[4] = acc1[4] * inv1 + b1.x; r[5] = acc1[5] * inv1 + b1.y;
        r[6] = acc1[6] * inv1 + b1.z; r[7] = acc1[7] * inv1 + b1.w;
        uint4 q;
        __half2* hp = (__half2*)&q;
        #pragma unroll
        for (int e = 0; e < 4; e++) {
            float x0 = r[2 * e], x1 = r[2 * e + 1];
            x0 = x0 > 0.f ? x0 : (__expf(x0) - 1.f);
            x1 = x1 > 0.f ? x1 : (__expf(x1) - 1.f);
            hp[e] = __floats2half2_rn(x0, x1);
        }
        ov[c1] = q;
    }
}

__global__ void k_agg256(const __half* __restrict__ hbuf,
                         const float* __restrict__ als,
                         const float* __restrict__ ald,
                         const float* __restrict__ bias,
                         __half* __restrict__ out) {
    int w = (blockIdx.x * blockDim.x + threadIdx.x) >> 5;
    int lane = threadIdx.x & 31;
    if (w >= NN) return;

    float ad = __ldg(ald + w);
    float m = leaky02(__ldg(als + w) + ad);
    float dnm = 1.f;
    const uint4* hv = (const uint4*)(hbuf + (size_t)w * OUTC);
    float acc[8];
    unpack8(hv[lane], acc);

    int beg = g_off[w], end = g_off[w + 1];
    if (beg < end) {
        int u1 = g_csrc[beg];
        float a1 = __ldg(als + u1);
        uint4 q1 = __ldg((const uint4*)(hbuf + (size_t)u1 * OUTC) + lane);
        for (int p = beg; p < end; p++) {
            int pn = (p + 1 < end) ? p + 1 : p;
            int u2 = g_csrc[pn];
            float a2 = __ldg(als + u2);
            uint4 q2 = __ldg((const uint4*)(hbuf + (size_t)u2 * OUTC) + lane);

            float e = leaky02(a1 + ad);
            float sh, wh;
            if (e > m) {
                sh = __expf(m - e); wh = 1.f; m = e;
            } else {
                sh = 1.f; wh = __expf(e - m);
            }
            dnm = dnm * sh + wh;
            float v[8];
            unpack8(q1, v);
            #pragma unroll
            for (int e2 = 0; e2 < 8; e2++) acc[e2] = acc[e2] * sh + wh * v[e2];
            a1 = a2; q1 = q2;
        }
    }
    float inv = 1.f / dnm;
    int base = 8 * lane;
    float4 b0 = __ldg((const float4*)(bias + base));
    float4 b1 = __ldg((const float4*)(bias + base + 4));
    float r[8];
    r[0] = acc[0] * inv + b0.x; r[1] = acc[1] * inv + b0.y;
    r[2] = acc[2] * inv + b0.z; r[3] = acc[3] * inv + b0.w;
    r[4] = acc[4] * inv + b1.x; r[5] = acc[5] * inv + b1.y;
    r[6] = acc[6] * inv + b1.z; r[7] = acc[7] * inv + b1.w;
    uint4 q;
    __half2* hp = (__half2*)&q;
    #pragma unroll
    for (int e2 = 0; e2 < 4; e2++)
        hp[e2] = __floats2half2_rn(r[2 * e2], r[2 * e2 + 1]);
    ((uint4*)(out + (size_t)w * OUTC))[lane] = q;
}

// ================= all-fp16 tensor-core GEMM =================================
// C = act(A[M,K] @ BT^T + bias); A fp16 row-major [M][K]; BT fp16 [N][K].
// Block 128x128x32, 128 threads (4 warps, each 64x64), 2 CTAs/SM co-resident
// so one CTA's HMMAs cover the other's barrier/cp.async bubbles.
#define GBM 128
#define GBN 128
#define GBK 32
#define AROW_U 20                 // uint32 per smem row: 16 data + 4 pad
#define A_U (GBM * AROW_U)        // 2560 uint32 per stage
#define B_U (GBN * AROW_U)        // 2560 uint32 per stage
#define GEMM_SMEM ((2 * A_U + 2 * B_U) * 4)   // 40960 B

__device__ __forceinline__ void cpa16(uint32_t* smem, const __half* g, int sz) {
    uint32_t s = (uint32_t)__cvta_generic_to_shared(smem);
    asm volatile("cp.async.cg.shared.global [%0], [%1], 16, %2;\n"
                 :: "r"(s), "l"(g), "r"(sz));
}
__device__ __forceinline__ void cpcommit() { asm volatile("cp.async.commit_group;\n"); }
__device__ __forceinline__ void cpwait1()  { asm volatile("cp.async.wait_group 1;\n" ::: "memory"); }

__global__ void __launch_bounds__(128, 2)
k_gemm_h(const __half* __restrict__ A, const __half* __restrict__ BT,
         const float* __restrict__ bias, float* __restrict__ Cf,
         __half* __restrict__ Ch, int M, int K, int Nn, int act) {
    extern __shared__ uint32_t smu[];
    uint32_t* Asm = smu;                 // [2][GBM][AROW_U]
    uint32_t* Bsm = smu + 2 * A_U;       // [2][GBN][AROW_U]
    int t = threadIdx.x;
    int lane = t & 31, wid = t >> 5;     // 4 warps
    int grp = lane >> 2, kq = lane & 3;
    int wm0 = (wid >> 1) * 64;
    int wn0 = (wid & 1) * 64;
    int row0 = blockIdx.y * GBM;
    int col0 = blockIdx.x * GBN;

    float acc[4][8][4];
    #pragma unroll
    for (int i = 0; i < 4; i++)
        #pragma unroll
        for (int j = 0; j < 8; j++)
            #pragma unroll
            for (int q = 0; q < 4; q++) acc[i][j][q] = 0.f;

    // A tile: 128 rows x 32 halves = 512 16B-chunks -> 4/thread; B same
    int aRow[4], aKo[4];
    #pragma unroll
    for (int i = 0; i < 4; i++) { int c = i * 128 + t; aRow[i] = c >> 2; aKo[i] = (c & 3) * 8; }

    auto loadTile = [&](int it, int buf) {
        int k0 = it * GBK;
        #pragma unroll
        for (int i = 0; i < 4; i++) {
            int r = row0 + aRow[i];
            int sz = (r < M) ? 16 : 0;
            const __half* src = A + (size_t)(sz ? r : 0) * K + k0 + aKo[i];
            cpa16(Asm + buf * A_U + aRow[i] * AROW_U + aKo[i] / 2, src, sz);
        }
        #pragma unroll
        for (int i = 0; i < 4; i++) {
            const __half* src = BT + (size_t)(col0 + aRow[i]) * K + k0 + aKo[i];
            cpa16(Bsm + buf * B_U + aRow[i] * AROW_U + aKo[i] / 2, src, 16);
        }
    };

    int nIter = K / GBK;
    loadTile(0, 0);
    cpcommit();
    int buf = 0;
    for (int it = 0; it < nIter; ++it) {
        if (it + 1 < nIter) loadTile(it + 1, buf ^ 1);
        cpcommit();
        cpwait1();
        __syncthreads();
        const uint32_t* Ab = Asm + buf * A_U;
        const uint32_t* Bb = Bsm + buf * B_U;
        #pragma unroll
        for (int s = 0; s < 2; ++s) {          // two m16n8k16 steps per k32 tile
            uint32_t af[4][4], bf[8][2];
            #pragma unroll
            for (int mt = 0; mt < 4; mt++) {
                int m = wm0 + mt * 16 + grp;
                const uint32_t* r0 = Ab + m * AROW_U + 8 * s;
                const uint32_t* r1 = r0 + 8 * AROW_U;
                af[mt][0] = r0[kq];
                af[mt][1] = r1[kq];
                af[mt][2] = r0[kq + 4];
                af[mt][3] = r1[kq + 4];
            }
            #pragma unroll
            for (int nt = 0; nt < 8; nt++) {
                int n = wn0 + nt * 8 + grp;
                const uint32_t* rb = Bb + n * AROW_U + 8 * s;
                bf[nt][0] = rb[kq];
                bf[nt][1] = rb[kq + 4];
            }
            #pragma unroll
            for (int mt = 0; mt < 4; mt++)
                #pragma unroll
                for (int nt = 0; nt < 8; nt++)
                    asm volatile(
                        "mma.sync.aligned.m16n8k16.row.col.f32.f16.f16.f32 "
                        "{%0,%1,%2,%3},{%4,%5,%6,%7},{%8,%9},{%0,%1,%2,%3};"
                        : "+f"(acc[mt][nt][0]), "+f"(acc[mt][nt][1]),
                          "+f"(acc[mt][nt][2]), "+f"(acc[mt][nt][3])
                        : "r"(af[mt][0]), "r"(af[mt][1]), "r"(af[mt][2]), "r"(af[mt][3]),
                          "r"(bf[nt][0]), "r"(bf[nt][1]));
        }
        __syncthreads();
        buf ^= 1;
    }

    // epilogue: c0,c1 -> row grp; c2,c3 -> row grp+8; cols 2*kq, 2*kq+1
    #pragma unroll
    for (int mt = 0; mt < 4; mt++) {
        #pragma unroll
        for (int half = 0; half < 2; half++) {
            int r = row0 + wm0 + mt * 16 + grp + half * 8;
            if (r < M) {
                #pragma unroll
                for (int nt = 0; nt < 8; nt++) {
                    int cix = col0 + wn0 + nt * 8 + 2 * kq;
                    float v0 = acc[mt][nt][half * 2 + 0];
                    float v1 = acc[mt][nt][half * 2 + 1];
                    if (bias) { v0 += __ldg(bias + cix); v1 += __ldg(bias + cix + 1); }
                    if (act)  { v0 = fmaxf(v0, 0.f); v1 = fmaxf(v1, 0.f); }
                    if (Ch) {
                        *(__half2*)(Ch + (size_t)r * Nn + cix) = __floats2half2_rn(v0, v1);
                    } else {
                        *(float2*)(Cf + (size_t)r * Nn + cix) = make_float2(v0, v1);
                    }
                }
            }
        }
    }
}

// ---------------- launch ----------------------------------------------------
extern "C" void kernel_launch(void* const* d_in, const int* in_sizes, int n_in,
                              void* d_out, int out_size) {
    const float* x   = (const float*)d_in[0];
    const int*   ei  = (const int*)d_in[1];
    const float* W1  = (const float*)d_in[2];
    const float* as1 = (const float*)d_in[3];
    const float* ad1 = (const float*)d_in[4];
    const float* b1  = (const float*)d_in[5];
    const float* W2  = (const float*)d_in[6];
    const float* as2 = (const float*)d_in[7];
    const float* ad2 = (const float*)d_in[8];
    const float* b2  = (const float*)d_in[9];
    const float* W3  = (const float*)d_in[10];
    const float* as3 = (const float*)d_in[11];
    const float* ad3 = (const float*)d_in[12];
    const float* b3  = (const float*)d_in[13];
    const float* M1  = (const float*)d_in[14];
    const float* mb1 = (const float*)d_in[15];
    const float* M2  = (const float*)d_in[16];
    const float* mb2 = (const float*)d_in[17];
    const float* M3  = (const float*)d_in[18];
    const float* mb3 = (const float*)d_in[19];
    float* out = (float*)d_out;

    __half *h16, *f16, *x16, *w16;
    float *als, *ald;
    cudaGetSymbolAddress((void**)&h16, g_h16);
    cudaGetSymbolAddress((void**)&f16, g_f16);
    cudaGetSymbolAddress((void**)&x16, g_x16);
    cudaGetSymbolAddress((void**)&w16, g_w16);
    cudaGetSymbolAddress((void**)&als, g_als);
    cudaGetSymbolAddress((void**)&ald, g_ald);

    static bool attr_done = false;
    if (!attr_done) {
        cudaFuncSetAttribute(k_gemm_h,
                             cudaFuncAttributeMaxDynamicSharedMemorySize, GEMM_SMEM);
        attr_done = true;
    }

    const int TB = 256;
    int nodeBlocks = (NN + TB - 1) / TB;
    int edgeBlocks = (EDGES + TB - 1) / TB;
    int warpBlocks = (NN * 32 + TB - 1) / TB;

    // ---- fp16 conversions: x and transposed weights ----
    int xn4 = NN * F_IN / 4;
    k_cvt4<<<(xn4 + TB - 1) / TB, TB>>>(x, x16, xn4);
    k_cvt_wT<<<(256 * 512 + TB - 1) / TB, TB>>>(W1, w16 + OFF_W1T, 256, 512);
    k_cvt_wT<<<(512 * 512 + TB - 1) / TB, TB>>>(W2, w16 + OFF_W2T, 512, 512);
    k_cvt_wT<<<(512 * 256 + TB - 1) / TB, TB>>>(W3, w16 + OFF_W3T, 512, 256);
    k_cvt_wT<<<(256 * 256 + TB - 1) / TB, TB>>>(M1, w16 + OFF_M1T, 256, 256);
    k_cvt_wT<<<(256 * 128 + TB - 1) / TB, TB>>>(M2, w16 + OFF_M2T, 256, 128);
    k_cvt_wT<<<(128 * 256 + TB - 1) / TB, TB>>>(M3, w16 + OFF_M3T, 128, 256);

    // ---- CSR by dst ----
    k_zero_deg<<<nodeBlocks, TB>>>();
    k_count<<<edgeBlocks, TB>>>(ei);
    k_scan<<<1, 1024>>>();          // also writes g_cur
    k_scatter<<<edgeBlocks, TB>>>(ei);

    int mBlk = (NN + GBM - 1) / GBM;   // 391

    // ---- GAT layer 1: x16[N,256] @ W1 -> h16[N,512] ----
    k_gemm_h<<<dim3(CATC / GBN, mBlk), 128, GEMM_SMEM>>>(
        x16, w16 + OFF_W1T, nullptr, nullptr, h16, NN, F_IN, CATC, 0);
    k_alpha4<<<warpBlocks, TB>>>(h16, as1, ad1, als, ald);
    k_agg512<<<warpBlocks, TB>>>(h16, als, ald, b1, f16);   // +b1, ELU

    // ---- GAT layer 2: f16[N,512] @ W2 -> h16[N,512] ----
    k_gemm_h<<<dim3(CATC / GBN, mBlk), 128, GEMM_SMEM>>>(
        f16, w16 + OFF_W2T, nullptr, nullptr, h16, NN, CATC, CATC, 0);
    k_alpha4<<<warpBlocks, TB>>>(h16, as2, ad2, als, ald);
    k_agg512<<<warpBlocks, TB>>>(h16, als, ald, b2, f16);   // +b2, ELU

    // ---- GAT layer 3: f16[N,512] @ W3 -> h16[N,256], 1 head ----
    k_gemm_h<<<dim3(OUTC / GBN, mBlk), 128, GEMM_SMEM>>>(
        f16, w16 + OFF_W3T, nullptr, nullptr, h16, NN, CATC, OUTC, 0);
    k_alpha1<<<warpBlocks, TB>>>(h16, as3, ad3, als, ald);
    k_agg256<<<warpBlocks, TB>>>(h16, als, ald, b3, f16);   // +b3

    // ---- MLP ----
    k_gemm_h<<<dim3(256 / GBN, mBlk), 128, GEMM_SMEM>>>(
        f16, w16 + OFF_M1T, mb1, nullptr, h16, NN, 256, 256, 1);   // ReLU
    k_gemm_h<<<dim3(128 / GBN, mBlk), 128, GEMM_SMEM>>>(
        h16, w16 + OFF_M2T, mb2, nullptr, f16, NN, 256, 128, 1);   // ReLU
    k_gemm_h<<<dim3(256 / GBN, mBlk), 128, GEMM_SMEM>>>(
        f16, w16 + OFF_M3T, mb3, out, nullptr, NN, 128, 256, 0);   // fp32 out
}

// round 14
// speedup vs baseline: 2.5889x; 1.0050x over previous
#include <cuda_runtime.h>
#include <cuda_fp16.h>
#include <cstdint>
#include <math.h>

// Problem constants (fixed by reference)
#define NN     50000
#define EDGES  800000
#define F_IN   256
#define HIDC   128
#define NHEAD  4
#define CATC   512   // NHEAD*HIDC
#define OUTC   256

// ---------------- device scratch (static globals; no allocation) ------------
__device__ __align__(16) __half g_h16[(size_t)NN * CATC];   // GEMM outputs (51.2 MB)
__device__ __align__(16) __half g_f16[(size_t)NN * CATC];   // aggregated feats (51.2 MB)
__device__ __align__(16) __half g_x16[(size_t)NN * F_IN];   // fp16 copy of x (25.6 MB)
__device__ __align__(16) __half g_w16[655360];              // fp16 transposed weights
__device__ float g_als[NN * NHEAD];
__device__ float g_ald[NN * NHEAD];
__device__ int   g_deg[NN];
__device__ int   g_cur[NN];
__device__ int   g_off[NN + 1];
__device__ int   g_csrc[EDGES];

#define OFF_W1T 0
#define OFF_W2T 131072
#define OFF_W3T 393216
#define OFF_M1T 524288
#define OFF_M2T 589824
#define OFF_M3T 622592

// ---------------- conversion kernels ----------------------------------------
__global__ void k_cvt4(const float* __restrict__ src, __half* __restrict__ dst, int n4) {
    int i = blockIdx.x * blockDim.x + threadIdx.x;
    if (i < n4) {
        float4 v = ((const float4*)src)[i];
        ((__half2*)dst)[2 * i]     = __floats2half2_rn(v.x, v.y);
        ((__half2*)dst)[2 * i + 1] = __floats2half2_rn(v.z, v.w);
    }
}

__global__ void k_cvt_wT(const float* __restrict__ src, __half* __restrict__ dst,
                         int K, int Nc) {
    int id = blockIdx.x * blockDim.x + threadIdx.x;
    if (id < K * Nc) {
        int k = id % K, n = id / K;
        dst[id] = __float2half_rn(src[k * Nc + n]);
    }
}

// ---------------- CSR build -------------------------------------------------
__global__ void k_zero_deg() {
    int i = blockIdx.x * blockDim.x + threadIdx.x;
    if (i < NN) g_deg[i] = 0;
}

__global__ void k_zero_alpha() {
    int i = blockIdx.x * blockDim.x + threadIdx.x;
    if (i < NN * NHEAD) { g_als[i] = 0.f; g_ald[i] = 0.f; }
}

__global__ void k_count(const int* __restrict__ ei) {
    int e = blockIdx.x * blockDim.x + threadIdx.x;
    if (e < EDGES) atomicAdd(&g_deg[ei[EDGES + e]], 1);
}

__global__ void k_scan() {
    __shared__ int wsum[32];
    __shared__ int carry_s;
    int t = threadIdx.x;
    int lane = t & 31, wid = t >> 5;
    if (t == 0) carry_s = 0;
    __syncthreads();
    for (int base = 0; base < NN; base += 1024) {
        int i = base + t;
        int v = (i < NN) ? g_deg[i] : 0;
        int x = v;
        #pragma unroll
        for (int o = 1; o < 32; o <<= 1) {
            int y = __shfl_up_sync(0xFFFFFFFFu, x, o);
            if (lane >= o) x += y;
        }
        if (lane == 31) wsum[wid] = x;
        __syncthreads();
        if (wid == 0) {
            int ws = wsum[lane];
            #pragma unroll
            for (int o = 1; o < 32; o <<= 1) {
                int y = __shfl_up_sync(0xFFFFFFFFu, ws, o);
                if (lane >= o) ws += y;
            }
            wsum[lane] = ws;
        }
        __syncthreads();
        int incl = x + (wid ? wsum[wid - 1] : 0);
        int total = wsum[31];
        int carry = carry_s;
        if (i < NN) {
            int off = carry + incl - v;
            g_off[i] = off;
            g_cur[i] = off;
        }
        __syncthreads();
        if (t == 0) carry_s = carry + total;
        __syncthreads();
    }
    if (t == 0) g_off[NN] = carry_s;
}

__global__ void k_scatter(const int* __restrict__ ei) {
    int e = blockIdx.x * blockDim.x + threadIdx.x;
    if (e < EDGES) {
        int s = ei[e], d = ei[EDGES + e];
        int p = atomicAdd(&g_cur[d], 1);
        g_csrc[p] = s;
    }
}

__device__ __forceinline__ float leaky02(float x) { return x > 0.f ? x : 0.2f * x; }

__device__ __forceinline__ void unpack8(uint4 q, float* f) {
    const __half2* hp = (const __half2*)&q;
    float2 a = __half22float2(hp[0]); f[0] = a.x; f[1] = a.y;
    float2 b = __half22float2(hp[1]); f[2] = b.x; f[3] = b.y;
    float2 c = __half22float2(hp[2]); f[4] = c.x; f[5] = c.y;
    float2 d = __half22float2(hp[3]); f[6] = d.x; f[7] = d.y;
}

// ---------------- per-dst segment softmax + weighted aggregation ------------
__global__ void k_agg512(const __half* __restrict__ hbuf,
                         const float* __restrict__ als,
                         const float* __restrict__ ald,
                         const float* __restrict__ bias,
                         __half* __restrict__ out) {
    int w = (blockIdx.x * blockDim.x + threadIdx.x) >> 5;
    int lane = threadIdx.x & 31;
    if (w >= NN) return;

    float4 adv = __ldg((const float4*)(ald + 4 * w));
    float ad[4] = {adv.x, adv.y, adv.z, adv.w};
    float4 asv = __ldg((const float4*)(als + 4 * w));
    float m[4], dnm[4];
    m[0] = leaky02(asv.x + ad[0]); m[1] = leaky02(asv.y + ad[1]);
    m[2] = leaky02(asv.z + ad[2]); m[3] = leaky02(asv.w + ad[3]);
    dnm[0] = dnm[1] = dnm[2] = dnm[3] = 1.f;

    int c0 = lane, c1 = 32 + lane;
    int hd0 = c0 >> 4, hd1 = c1 >> 4;
    const uint4* hv = (const uint4*)(hbuf + (size_t)w * CATC);
    float acc0[8], acc1[8];
    unpack8(hv[c0], acc0);            // self loop seeds (weight 1)
    unpack8(hv[c1], acc1);

    int beg = g_off[w], end = g_off[w + 1];
    if (beg < end) {
        int u1 = g_csrc[beg];
        float4 a1 = __ldg((const float4*)(als + 4 * u1));
        const uint4* hu1 = (const uint4*)(hbuf + (size_t)u1 * CATC);
        uint4 q1a = __ldg(hu1 + c0);
        uint4 q1b = __ldg(hu1 + c1);

        for (int p = beg; p < end; p++) {
            int pn = (p + 1 < end) ? p + 1 : p;
            int u2 = g_csrc[pn];
            float4 a2 = __ldg((const float4*)(als + 4 * u2));
            const uint4* hu2 = (const uint4*)(hbuf + (size_t)u2 * CATC);
            uint4 q2a = __ldg(hu2 + c0);
            uint4 q2b = __ldg(hu2 + c1);

            float ev[4] = {leaky02(a1.x + ad[0]), leaky02(a1.y + ad[1]),
                           leaky02(a1.z + ad[2]), leaky02(a1.w + ad[3])};
            float sh[4], wh[4];
            #pragma unroll
            for (int hh = 0; hh < 4; hh++) {
                float e = ev[hh];
                if (e > m[hh]) {
                    sh[hh] = __expf(m[hh] - e);
                    wh[hh] = 1.f;
                    m[hh] = e;
                } else {
                    sh[hh] = 1.f;
                    wh[hh] = __expf(e - m[hh]);
                }
                dnm[hh] = dnm[hh] * sh[hh] + wh[hh];
            }
            float v0[8], v1[8];
            unpack8(q1a, v0);
            unpack8(q1b, v1);
            float s0 = sh[hd0], w0 = wh[hd0];
            float s1 = sh[hd1], w1 = wh[hd1];
            #pragma unroll
            for (int e = 0; e < 8; e++) {
                acc0[e] = acc0[e] * s0 + w0 * v0[e];
                acc1[e] = acc1[e] * s1 + w1 * v1[e];
            }
            a1 = a2; q1a = q2a; q1b = q2b;
        }
    }

    uint4* ov = (uint4*)(out + (size_t)w * CATC);
    float inv0 = 1.f / dnm[hd0], inv1 = 1.f / dnm[hd1];
    {
        int base = 8 * c0;
        float4 b0 = __ldg((const float4*)(bias + base));
        float4 b1 = __ldg((const float4*)(bias + base + 4));
        float r[8];
        r[0] = acc0[0] * inv0 + b0.x; r[1] = acc0[1] * inv0 + b0.y;
        r[2] = acc0[2] * inv0 + b0.z; r[3] = acc0[3] * inv0 + b0.w;
        r[4] = acc0[4] * inv0 + b1.x; r[5] = acc0[5] * inv0 + b1.y;
        r[6] = acc0[6] * inv0 + b1.z; r[7] = acc0[7] * inv0 + b1.w;
        uint4 q;
        __half2* hp = (__half2*)&q;
        #pragma unroll
        for (int e = 0; e < 4; e++) {
            float x0 = r[2 * e], x1 = r[2 * e + 1];
            x0 = x0 > 0.f ? x0 : (__expf(x0) - 1.f);   // ELU
            x1 = x1 > 0.f ? x1 : (__expf(x1) - 1.f);
            hp[e] = __floats2half2_rn(x0, x1);
        }
        ov[c0] = q;
    }
    {
        int base = 8 * c1;
        float4 b0 = __ldg((const float4*)(bias + base));
        float4 b1 = __ldg((const float4*)(bias + base + 4));
        float r[8];
        r[0] = acc1[0] * inv1 + b0.x; r[1] = acc1[1] * inv1 + b0.y;
        r[2] = acc1[2] * inv1 + b0.z; r[3] = acc1[3] * inv1 + b0.w;
        r[4] = acc1[4] * inv1 + b1.x; r[5] = acc1[5] * inv1 + b1.y;
        r[6] = acc1[6] * inv1 + b1.z; r[7] = acc1[7] * inv1 + b1.w;
        uint4 q;
        __half2* hp = (__half2*)&q;
        #pragma unroll
        for (int e = 0; e < 4; e++) {
            float x0 = r[2 * e], x1 = r[2 * e + 1];
            x0 = x0 > 0.f ? x0 : (__expf(x0) - 1.f);
            x1 = x1 > 0.f ? x1 : (__expf(x1) - 1.f);
            hp[e] = __floats2half2_rn(x0, x1);
        }
        ov[c1] = q;
    }
}

__global__ void k_agg256(const __half* __restrict__ hbuf,
                         const float* __restrict__ als,
                         const float* __restrict__ ald,
                         const float* __restrict__ bias,
                         __half* __restrict__ out) {
    int w = (blockIdx.x * blockDim.x + threadIdx.x) >> 5;
    int lane = threadIdx.x & 31;
    if (w >= NN) return;

    float ad = __ldg(ald + w);
    float m = leaky02(__ldg(als + w) + ad);
    float dnm = 1.f;
    const uint4* hv = (const uint4*)(hbuf + (size_t)w * OUTC);
    float acc[8];
    unpack8(hv[lane], acc);

    int beg = g_off[w], end = g_off[w + 1];
    if (beg < end) {
        int u1 = g_csrc[beg];
        float a1 = __ldg(als + u1);
        uint4 q1 = __ldg((const uint4*)(hbuf + (size_t)u1 * OUTC) + lane);
        for (int p = beg; p < end; p++) {
            int pn = (p + 1 < end) ? p + 1 : p;
            int u2 = g_csrc[pn];
            float a2 = __ldg(als + u2);
            uint4 q2 = __ldg((const uint4*)(hbuf + (size_t)u2 * OUTC) + lane);

            float e = leaky02(a1 + ad);
            float sh, wh;
            if (e > m) {
                sh = __expf(m - e); wh = 1.f; m = e;
            } else {
                sh = 1.f; wh = __expf(e - m);
            }
            dnm = dnm * sh + wh;
            float v[8];
            unpack8(q1, v);
            #pragma unroll
            for (int e2 = 0; e2 < 8; e2++) acc[e2] = acc[e2] * sh + wh * v[e2];
            a1 = a2; q1 = q2;
        }
    }
    float inv = 1.f / dnm;
    int base = 8 * lane;
    float4 b0 = __ldg((const float4*)(bias + base));
    float4 b1 = __ldg((const float4*)(bias + base + 4));
    float r[8];
    r[0] = acc[0] * inv + b0.x; r[1] = acc[1] * inv + b0.y;
    r[2] = acc[2] * inv + b0.z; r[3] = acc[3] * inv + b0.w;
    r[4] = acc[4] * inv + b1.x; r[5] = acc[5] * inv + b1.y;
    r[6] = acc[6] * inv + b1.z; r[7] = acc[7] * inv + b1.w;
    uint4 q;
    __half2* hp = (__half2*)&q;
    #pragma unroll
    for (int e2 = 0; e2 < 4; e2++)
        hp[e2] = __floats2half2_rn(r[2 * e2], r[2 * e2 + 1]);
    ((uint4*)(out + (size_t)w * OUTC))[lane] = q;
}

// ================= fp16 mma.sync GEMM with fused alpha =======================
// C = act(A[M,K] @ BT^T + bias); A fp16 [M][K], BT fp16 [N][K].
// Block 128x128x32, 128 threads (4 warps, 64x64 each), 2 CTAs/SM.
// aflag: 0=none, 1=multi-head alpha (head=col0>>7), 2=single-head alpha.
// Alpha: per-row dots with avs/avd accumulated via quad-shuffle + atomicAdd.
#define GBM 128
#define GBN 128
#define GBK 32
#define AROW_U 20                 // uint32 per smem row: 16 data + 4 pad
#define A_U (GBM * AROW_U)
#define B_U (GBN * AROW_U)
#define GEMM_SMEM ((2 * A_U + 2 * B_U) * 4)   // 40960 B

__device__ __forceinline__ void cpa16(uint32_t* smem, const __half* g, int sz) {
    uint32_t s = (uint32_t)__cvta_generic_to_shared(smem);
    asm volatile("cp.async.cg.shared.global [%0], [%1], 16, %2;\n"
                 :: "r"(s), "l"(g), "r"(sz));
}
__device__ __forceinline__ void cpcommit() { asm volatile("cp.async.commit_group;\n"); }
__device__ __forceinline__ void cpwait1()  { asm volatile("cp.async.wait_group 1;\n" ::: "memory"); }

__global__ void __launch_bounds__(128, 2)
k_gemm_h(const __half* __restrict__ A, const __half* __restrict__ BT,
         const float* __restrict__ bias, float* __restrict__ Cf,
         __half* __restrict__ Ch, int M, int K, int Nn, int act,
         int aflag, const float* __restrict__ avs, const float* __restrict__ avd,
         float* __restrict__ als, float* __restrict__ ald) {
    extern __shared__ uint32_t smu[];
    uint32_t* Asm = smu;
    uint32_t* Bsm = smu + 2 * A_U;
    int t = threadIdx.x;
    int lane = t & 31, wid = t >> 5;
    int grp = lane >> 2, kq = lane & 3;
    int wm0 = (wid >> 1) * 64;
    int wn0 = (wid & 1) * 64;
    int row0 = blockIdx.y * GBM;
    int col0 = blockIdx.x * GBN;

    float acc[4][8][4];
    #pragma unroll
    for (int i = 0; i < 4; i++)
        #pragma unroll
        for (int j = 0; j < 8; j++)
            #pragma unroll
            for (int q = 0; q < 4; q++) acc[i][j][q] = 0.f;

    int aRow[4], aKo[4];
    #pragma unroll
    for (int i = 0; i < 4; i++) { int c = i * 128 + t; aRow[i] = c >> 2; aKo[i] = (c & 3) * 8; }

    auto loadTile = [&](int it, int buf) {
        int k0 = it * GBK;
        #pragma unroll
        for (int i = 0; i < 4; i++) {
            int r = row0 + aRow[i];
            int sz = (r < M) ? 16 : 0;
            const __half* src = A + (size_t)(sz ? r : 0) * K + k0 + aKo[i];
            cpa16(Asm + buf * A_U + aRow[i] * AROW_U + aKo[i] / 2, src, sz);
        }
        #pragma unroll
        for (int i = 0; i < 4; i++) {
            const __half* src = BT + (size_t)(col0 + aRow[i]) * K + k0 + aKo[i];
            cpa16(Bsm + buf * B_U + aRow[i] * AROW_U + aKo[i] / 2, src, 16);
        }
    };

    int nIter = K / GBK;
    loadTile(0, 0);
    cpcommit();
    int buf = 0;
    for (int it = 0; it < nIter; ++it) {
        if (it + 1 < nIter) loadTile(it + 1, buf ^ 1);
        cpcommit();
        cpwait1();
        __syncthreads();
        const uint32_t* Ab = Asm + buf * A_U;
        const uint32_t* Bb = Bsm + buf * B_U;
        #pragma unroll
        for (int s = 0; s < 2; ++s) {
            uint32_t af[4][4], bf[8][2];
            #pragma unroll
            for (int mt = 0; mt < 4; mt++) {
                int m = wm0 + mt * 16 + grp;
                const uint32_t* r0 = Ab + m * AROW_U + 8 * s;
                const uint32_t* r1 = r0 + 8 * AROW_U;
                af[mt][0] = r0[kq];
                af[mt][1] = r1[kq];
                af[mt][2] = r0[kq + 4];
                af[mt][3] = r1[kq + 4];
            }
            #pragma unroll
            for (int nt = 0; nt < 8; nt++) {
                int n = wn0 + nt * 8 + grp;
                const uint32_t* rb = Bb + n * AROW_U + 8 * s;
                bf[nt][0] = rb[kq];
                bf[nt][1] = rb[kq + 4];
            }
            #pragma unroll
            for (int mt = 0; mt < 4; mt++)
                #pragma unroll
                for (int nt = 0; nt < 8; nt++)
                    asm volatile(
                        "mma.sync.aligned.m16n8k16.row.col.f32.f16.f16.f32 "
                        "{%0,%1,%2,%3},{%4,%5,%6,%7},{%8,%9},{%0,%1,%2,%3};"
                        : "+f"(acc[mt][nt][0]), "+f"(acc[mt][nt][1]),
                          "+f"(acc[mt][nt][2]), "+f"(acc[mt][nt][3])
                        : "r"(af[mt][0]), "r"(af[mt][1]), "r"(af[mt][2]), "r"(af[mt][3]),
                          "r"(bf[nt][0]), "r"(bf[nt][1]));
        }
        __syncthreads();
        buf ^= 1;
    }

    // epilogue: c0,c1 -> row grp; c2,c3 -> row grp+8; cols 2*kq, 2*kq+1
    // alpha: per-(mt,half) row dot with avs/avd over this warp's 64 cols,
    // quad-reduced (kq lanes share a row) then atomicAdd per row.
    #pragma unroll
    for (int mt = 0; mt < 4; mt++) {
        #pragma unroll
        for (int half = 0; half < 2; half++) {
            int r = row0 + wm0 + mt * 16 + grp + half * 8;
            bool rok = (r < M);
            float s_sum = 0.f, d_sum = 0.f;
            #pragma unroll
            for (int nt = 0; nt < 8; nt++) {
                int cix = col0 + wn0 + nt * 8 + 2 * kq;
                float v0 = acc[mt][nt][half * 2 + 0];   // raw h (OOB rows: 0)
                float v1 = acc[mt][nt][half * 2 + 1];
                if (aflag) {
                    s_sum += v0 * __ldg(avs + cix) + v1 * __ldg(avs + cix + 1);
                    d_sum += v0 * __ldg(avd + cix) + v1 * __ldg(avd + cix + 1);
                }
                if (rok) {
                    if (bias) { v0 += __ldg(bias + cix); v1 += __ldg(bias + cix + 1); }
                    if (act)  { v0 = fmaxf(v0, 0.f); v1 = fmaxf(v1, 0.f); }
                    if (Ch) {
                        *(__half2*)(Ch + (size_t)r * Nn + cix) = __floats2half2_rn(v0, v1);
                    } else {
                        *(float2*)(Cf + (size_t)r * Nn + cix) = make_float2(v0, v1);
                    }
                }
            }
            if (aflag) {
                s_sum += __shfl_xor_sync(0xFFFFFFFFu, s_sum, 1);
                s_sum += __shfl_xor_sync(0xFFFFFFFFu, s_sum, 2);
                d_sum += __shfl_xor_sync(0xFFFFFFFFu, d_sum, 1);
                d_sum += __shfl_xor_sync(0xFFFFFFFFu, d_sum, 2);
                if (rok && kq == 0) {
                    if (aflag == 1) {
                        int head = col0 >> 7;
                        atomicAdd(als + 4 * r + head, s_sum);
                        atomicAdd(ald + 4 * r + head, d_sum);
                    } else {
                        atomicAdd(als + r, s_sum);
                        atomicAdd(ald + r, d_sum);
                    }
                }
            }
        }
    }
}

// ---------------- launch ----------------------------------------------------
extern "C" void kernel_launch(void* const* d_in, const int* in_sizes, int n_in,
                              void* d_out, int out_size) {
    const float* x   = (const float*)d_in[0];
    const int*   ei  = (const int*)d_in[1];
    const float* W1  = (const float*)d_in[2];
    const float* as1 = (const float*)d_in[3];
    const float* ad1 = (const float*)d_in[4];
    const float* b1  = (const float*)d_in[5];
    const float* W2  = (const float*)d_in[6];
    const float* as2 = (const float*)d_in[7];
    const float* ad2 = (const float*)d_in[8];
    const float* b2  = (const float*)d_in[9];
    const float* W3  = (const float*)d_in[10];
    const float* as3 = (const float*)d_in[11];
    const float* ad3 = (const float*)d_in[12];
    const float* b3  = (const float*)d_in[13];
    const float* M1  = (const float*)d_in[14];
    const float* mb1 = (const float*)d_in[15];
    const float* M2  = (const float*)d_in[16];
    const float* mb2 = (const float*)d_in[17];
    const float* M3  = (const float*)d_in[18];
    const float* mb3 = (const float*)d_in[19];
    float* out = (float*)d_out;

    __half *h16, *f16, *x16, *w16;
    float *als, *ald;
    cudaGetSymbolAddress((void**)&h16, g_h16);
    cudaGetSymbolAddress((void**)&f16, g_f16);
    cudaGetSymbolAddress((void**)&x16, g_x16);
    cudaGetSymbolAddress((void**)&w16, g_w16);
    cudaGetSymbolAddress((void**)&als, g_als);
    cudaGetSymbolAddress((void**)&ald, g_ald);

    static cudaStream_t s1 = nullptr;
    static cudaEvent_t evFork = nullptr, evJoin = nullptr;
    if (!s1) {
        cudaFuncSetAttribute(k_gemm_h,
                             cudaFuncAttributeMaxDynamicSharedMemorySize, GEMM_SMEM);
        cudaStreamCreateWithFlags(&s1, cudaStreamNonBlocking);
        cudaEventCreateWithFlags(&evFork, cudaEventDisableTiming);
        cudaEventCreateWithFlags(&evJoin, cudaEventDisableTiming);
    }

    const int TB = 256;
    int nodeBlocks = (NN + TB - 1) / TB;
    int alphaBlocks = (NN * NHEAD + TB - 1) / TB;
    int edgeBlocks = (EDGES + TB - 1) / TB;
    int warpBlocks = (NN * 32 + TB - 1) / TB;
    int mBlk = (NN + GBM - 1) / GBM;   // 391

    // ---- fork: CSR build + remaining weight cvts on side stream ----
    cudaEventRecord(evFork, 0);
    cudaStreamWaitEvent(s1, evFork, 0);
    k_zero_deg<<<nodeBlocks, TB, 0, s1>>>();
    k_count<<<edgeBlocks, TB, 0, s1>>>(ei);
    k_scan<<<1, 1024, 0, s1>>>();
    k_scatter<<<edgeBlocks, TB, 0, s1>>>(ei);
    k_cvt_wT<<<(512 * 512 + TB - 1) / TB, TB, 0, s1>>>(W2, w16 + OFF_W2T, 512, 512);
    k_cvt_wT<<<(512 * 256 + TB - 1) / TB, TB, 0, s1>>>(W3, w16 + OFF_W3T, 512, 256);
    k_cvt_wT<<<(256 * 256 + TB - 1) / TB, TB, 0, s1>>>(M1, w16 + OFF_M1T, 256, 256);
    k_cvt_wT<<<(256 * 128 + TB - 1) / TB, TB, 0, s1>>>(M2, w16 + OFF_M2T, 256, 128);
    k_cvt_wT<<<(128 * 256 + TB - 1) / TB, TB, 0, s1>>>(M3, w16 + OFF_M3T, 128, 256);
    cudaEventRecord(evJoin, s1);

    // ---- main stream: layer-1 GEMM path ----
    int xn4 = NN * F_IN / 4;
    k_cvt4<<<(xn4 + TB - 1) / TB, TB>>>(x, x16, xn4);
    k_cvt_wT<<<(256 * 512 + TB - 1) / TB, TB>>>(W1, w16 + OFF_W1T, 256, 512);
    k_zero_alpha<<<alphaBlocks, TB>>>();
    k_gemm_h<<<dim3(CATC / GBN, mBlk), 128, GEMM_SMEM>>>(
        x16, w16 + OFF_W1T, nullptr, nullptr, h16, NN, F_IN, CATC, 0,
        1, as1, ad1, als, ald);

    cudaStreamWaitEvent(0, evJoin, 0);   // CSR + cvts ready

    k_agg512<<<warpBlocks, TB>>>(h16, als, ald, b1, f16);   // +b1, ELU

    // ---- GAT layer 2 ----
    k_zero_alpha<<<alphaBlocks, TB>>>();
    k_gemm_h<<<dim3(CATC / GBN, mBlk), 128, GEMM_SMEM>>>(
        f16, w16 + OFF_W2T, nullptr, nullptr, h16, NN, CATC, CATC, 0,
        1, as2, ad2, als, ald);
    k_agg512<<<warpBlocks, TB>>>(h16, als, ald, b2, f16);   // +b2, ELU

    // ---- GAT layer 3 (1 head) ----
    k_zero_alpha<<<alphaBlocks, TB>>>();
    k_gemm_h<<<dim3(OUTC / GBN, mBlk), 128, GEMM_SMEM>>>(
        f16, w16 + OFF_W3T, nullptr, nullptr, h16, NN, CATC, OUTC, 0,
        2, as3, ad3, als, ald);
    k_agg256<<<warpBlocks, TB>>>(h16, als, ald, b3, f16);   // +b3

    // ---- MLP ----
    k_gemm_h<<<dim3(256 / GBN, mBlk), 128, GEMM_SMEM>>>(
        f16, w16 + OFF_M1T, mb1, nullptr, h16, NN, 256, 256, 1,
        0, nullptr, nullptr, nullptr, nullptr);   // ReLU
    k_gemm_h<<<dim3(128 / GBN, mBlk), 128, GEMM_SMEM>>>(
        h16, w16 + OFF_M2T, mb2, nullptr, f16, NN, 256, 128, 1,
        0, nullptr, nullptr, nullptr, nullptr);   // ReLU
    k_gemm_h<<<dim3(256 / GBN, mBlk), 128, GEMM_SMEM>>>(
        f16, w16 + OFF_M3T, mb3, out, nullptr, NN, 128, 256, 0,
        0, nullptr, nullptr, nullptr, nullptr);   // fp32 out
}